// round 3
// baseline (speedup 1.0000x reference)
#include <cuda_runtime.h>
#include <cstdint>

#define HH 256
#define WW 256
#define NC 80
#define HWSZ 65536
#define KTOP 100
#define MAXCAND 8192

// scratch (no cudaMalloc allowed)
__device__ unsigned int        g_count[NC];
__device__ unsigned long long  g_cand[NC][MAXCAND];
__device__ unsigned int        g_topk_key[NC * KTOP];   // fkey(logit)
__device__ int                 g_topk_idx[NC * KTOP];   // spatial index in [0,65536)

// monotone float->uint key (handles negatives)
__device__ __forceinline__ unsigned int fkey(float f) {
    unsigned int b = __float_as_uint(f);
    return b ^ ((b & 0x80000000u) ? 0xFFFFFFFFu : 0x80000000u);
}
__device__ __forceinline__ float fkeyinv(unsigned int k) {
    unsigned int b = k ^ ((k & 0x80000000u) ? 0x80000000u : 0xFFFFFFFFu);
    return __uint_as_float(b);
}

__global__ void zero_counts_kernel() {
    if (threadIdx.x < NC) g_count[threadIdx.x] = 0u;
}

// 5x5 strict-window max (SAME, -inf pad) on logits of batch 0; compact survivors.
__global__ void suppress_kernel(const float* __restrict__ cls) {
    __shared__ float t[36][36 + 1];
    __shared__ float rmax[36][32 + 1];
    const int c  = blockIdx.z;
    const int x0 = blockIdx.x * 32, y0 = blockIdx.y * 32;
    const float* p = cls + (size_t)c * HWSZ;   // batch 0
    const int tid = threadIdx.y * 32 + threadIdx.x;

    for (int i = tid; i < 36 * 36; i += 1024) {
        int ly = i / 36, lx = i % 36;
        int gy = y0 + ly - 2, gx = x0 + lx - 2;
        float v = -__int_as_float(0x7f800000);  // -inf
        if (gy >= 0 && gy < HH && gx >= 0 && gx < WW) v = p[gy * WW + gx];
        t[ly][lx] = v;
    }
    __syncthreads();
    for (int i = tid; i < 36 * 32; i += 1024) {
        int ly = i / 32, lx = i % 32;
        float m = t[ly][lx];
        m = fmaxf(m, t[ly][lx + 1]);
        m = fmaxf(m, t[ly][lx + 2]);
        m = fmaxf(m, t[ly][lx + 3]);
        m = fmaxf(m, t[ly][lx + 4]);
        rmax[ly][lx] = m;
    }
    __syncthreads();
    const int lx = threadIdx.x, ly = threadIdx.y;
    float v = t[ly + 2][lx + 2];
    float m = rmax[ly][lx];
    m = fmaxf(m, rmax[ly + 1][lx]);
    m = fmaxf(m, rmax[ly + 2][lx]);
    m = fmaxf(m, rmax[ly + 3][lx]);
    m = fmaxf(m, rmax[ly + 4][lx]);
    if (v == m) {
        int idx = (y0 + ly) * WW + (x0 + lx);
        unsigned int pos = atomicAdd(&g_count[c], 1u);
        if (pos < MAXCAND)
            g_cand[c][pos] = ((unsigned long long)fkey(v) << 32)
                           | (unsigned int)(65535 - idx);   // lower idx => bigger key tail
    }
}

// per-class bitonic sort (descending) of candidates, emit top-100
__global__ void class_topk_kernel() {
    extern __shared__ unsigned long long s[];
    const int c = blockIdx.x;
    unsigned int cnt = g_count[c];
    if (cnt > MAXCAND) cnt = MAXCAND;
    int n = 128;
    while (n < (int)cnt) n <<= 1;

    for (int i = threadIdx.x; i < n; i += blockDim.x)
        s[i] = (i < (int)cnt) ? g_cand[c][i] : 0ULL;
    __syncthreads();

    for (int k = 2; k <= n; k <<= 1) {
        for (int j = k >> 1; j > 0; j >>= 1) {
            for (int i = threadIdx.x; i < n; i += blockDim.x) {
                int ixj = i ^ j;
                if (ixj > i) {
                    unsigned long long a = s[i], b = s[ixj];
                    bool up = ((i & k) == 0);
                    if (up ? (a < b) : (a > b)) { s[i] = b; s[ixj] = a; }
                }
            }
            __syncthreads();
        }
    }
    for (int k = threadIdx.x; k < KTOP; k += blockDim.x) {
        unsigned long long key = s[k];
        g_topk_key[c * KTOP + k] = (unsigned int)(key >> 32);
        g_topk_idx[c * KTOP + k] = 65535 - (int)(key & 0xFFFFu);
    }
}

// global top-100 over 80*100 entries + box decode + output write
__global__ void global_topk_kernel(const float* __restrict__ txty,
                                   const float* __restrict__ twth,
                                   float* __restrict__ out) {
    extern __shared__ unsigned long long s[];
    const int N = 8192;
    for (int i = threadIdx.x; i < N; i += blockDim.x) {
        if (i < NC * KTOP)
            s[i] = ((unsigned long long)g_topk_key[i] << 32)
                 | (unsigned int)(8191 - i);               // lower flat idx first on ties
        else
            s[i] = 0ULL;
    }
    __syncthreads();
    for (int k = 2; k <= N; k <<= 1) {
        for (int j = k >> 1; j > 0; j >>= 1) {
            for (int i = threadIdx.x; i < N; i += blockDim.x) {
                int ixj = i ^ j;
                if (ixj > i) {
                    unsigned long long a = s[i], b = s[ixj];
                    bool up = ((i & k) == 0);
                    if (up ? (a < b) : (a > b)) { s[i] = b; s[ixj] = a; }
                }
            }
            __syncthreads();
        }
    }
    if (threadIdx.x < KTOP) {
        const int t = threadIdx.x;
        unsigned long long key = s[t];
        unsigned int kb = (unsigned int)(key >> 32);
        int flat = 8191 - (int)(key & 0x1FFFu);
        int cls = flat / KTOP;
        int spatial = g_topk_idx[flat];
        float logit = fkeyinv(kb);
        float score = 1.0f / (1.0f + expf(-logit));

        int y = spatial >> 8, x = spatial & 255;
        float tx = txty[spatial];              // batch0, ch0
        float ty = txty[HWSZ + spatial];       // batch0, ch1
        float tw = twth[spatial];
        float th = twth[HWSZ + spatial];

        float cx = ((float)x + 1.0f / (1.0f + expf(-tx))) * 4.0f;
        float cy = ((float)y + 1.0f / (1.0f + expf(-ty))) * 4.0f;
        float w2 = expf(tw) * 2.0f;   // exp*stride/2
        float h2 = expf(th) * 2.0f;
        const float inv = 1.0f / 1024.0f;

        out[t * 4 + 0] = fminf(fmaxf((cx - w2) * inv, 0.0f), 1.0f);
        out[t * 4 + 1] = fminf(fmaxf((cy - h2) * inv, 0.0f), 1.0f);
        out[t * 4 + 2] = fminf(fmaxf((cx + w2) * inv, 0.0f), 1.0f);
        out[t * 4 + 3] = fminf(fmaxf((cy + h2) * inv, 0.0f), 1.0f);
        out[4 * KTOP + t] = score;
        out[5 * KTOP + t] = (float)cls;
    }
}

extern "C" void kernel_launch(void* const* d_in, const int* in_sizes, int n_in,
                              void* d_out, int out_size) {
    const float* cls  = (const float*)d_in[0];
    const float* txty = (const float*)d_in[1];
    const float* twth = (const float*)d_in[2];
    float* out = (float*)d_out;

    cudaFuncSetAttribute(class_topk_kernel,
                         cudaFuncAttributeMaxDynamicSharedMemorySize, 65536);
    cudaFuncSetAttribute(global_topk_kernel,
                         cudaFuncAttributeMaxDynamicSharedMemorySize, 65536);

    zero_counts_kernel<<<1, 128>>>();
    dim3 grid(WW / 32, HH / 32, NC);
    dim3 blk(32, 32);
    suppress_kernel<<<grid, blk>>>(cls);
    class_topk_kernel<<<NC, 512, 65536>>>();
    global_topk_kernel<<<1, 1024, 65536>>>(txty, twth, out);
}

// round 4
// speedup vs baseline: 1.7061x; 1.7061x over previous
#include <cuda_runtime.h>
#include <cstdint>

#define HH 256
#define WW 256
#define NC 80
#define HWSZ 65536
#define KTOP 100
#define MAXCAND 8192
#define SELCAP 1024

// scratch (no cudaMalloc allowed)
__device__ unsigned int        g_count[NC];
__device__ unsigned long long  g_cand[NC][MAXCAND];
__device__ unsigned int        g_topk_key[NC * KTOP];   // fkey(logit), sorted desc per class
__device__ int                 g_topk_idx[NC * KTOP];   // spatial index in [0,65536)

// monotone float->uint key (handles negatives)
__device__ __forceinline__ unsigned int fkey(float f) {
    unsigned int b = __float_as_uint(f);
    return b ^ ((b & 0x80000000u) ? 0xFFFFFFFFu : 0x80000000u);
}
__device__ __forceinline__ float fkeyinv(unsigned int k) {
    unsigned int b = k ^ ((k & 0x80000000u) ? 0x80000000u : 0xFFFFFFFFu);
    return __uint_as_float(b);
}

__global__ void zero_counts_kernel() {
    if (threadIdx.x < NC) g_count[threadIdx.x] = 0u;
}

// 5x5 strict-window max (SAME, -inf pad) on logits of batch 0; compact survivors.
__global__ void suppress_kernel(const float* __restrict__ cls) {
    __shared__ float t[36][36 + 1];
    __shared__ float rmax[36][32 + 1];
    const int c  = blockIdx.z;
    const int x0 = blockIdx.x * 32, y0 = blockIdx.y * 32;
    const float* p = cls + (size_t)c * HWSZ;   // batch 0
    const int tid = threadIdx.y * 32 + threadIdx.x;

    for (int i = tid; i < 36 * 36; i += 1024) {
        int ly = i / 36, lx = i % 36;
        int gy = y0 + ly - 2, gx = x0 + lx - 2;
        float v = -__int_as_float(0x7f800000);  // -inf
        if (gy >= 0 && gy < HH && gx >= 0 && gx < WW) v = p[gy * WW + gx];
        t[ly][lx] = v;
    }
    __syncthreads();
    for (int i = tid; i < 36 * 32; i += 1024) {
        int ly = i / 32, lx = i % 32;
        float m = t[ly][lx];
        m = fmaxf(m, t[ly][lx + 1]);
        m = fmaxf(m, t[ly][lx + 2]);
        m = fmaxf(m, t[ly][lx + 3]);
        m = fmaxf(m, t[ly][lx + 4]);
        rmax[ly][lx] = m;
    }
    __syncthreads();
    const int lx = threadIdx.x, ly = threadIdx.y;
    float v = t[ly + 2][lx + 2];
    float m = rmax[ly][lx];
    m = fmaxf(m, rmax[ly + 1][lx]);
    m = fmaxf(m, rmax[ly + 2][lx]);
    m = fmaxf(m, rmax[ly + 3][lx]);
    m = fmaxf(m, rmax[ly + 4][lx]);
    if (v == m) {
        int idx = (y0 + ly) * WW + (x0 + lx);
        unsigned int pos = atomicAdd(&g_count[c], 1u);
        if (pos < MAXCAND)
            g_cand[c][pos] = ((unsigned long long)fkey(v) << 32)
                           | (unsigned int)(65535 - idx);   // lower idx => bigger key tail
    }
}

// per-class top-100 via threshold quickselect + small bitonic sort.
// dynamic smem layout: [MAXCAND ull keys][SELCAP ull selected]
__global__ void class_topk_kernel() {
    extern __shared__ unsigned long long sk[];
    unsigned long long* sel = sk + MAXCAND;
    __shared__ int s_cnt;
    __shared__ int s_sel;
    __shared__ unsigned int s_thr;

    const int c   = blockIdx.x;
    const int tid = threadIdx.x;
    const int bd  = blockDim.x;

    unsigned int cnt = g_count[c];
    if (cnt > MAXCAND) cnt = MAXCAND;

    for (int i = tid; i < (int)cnt; i += bd) sk[i] = g_cand[c][i];
    if (tid == 0) { s_thr = 0u; s_sel = 0; }
    __syncthreads();

    // binary search on fkey threshold so that count(fkey >= T) in [KTOP, SELCAP]
    if (cnt > SELCAP) {
        unsigned int lo = 0u, hi = 0xFFFFFFFFu;
        for (int iter = 0; iter < 32; iter++) {
            if (hi - lo <= 1u) break;
            unsigned int mid = lo + ((hi - lo) >> 1);
            if (tid == 0) s_cnt = 0;
            __syncthreads();
            int loc = 0;
            for (int i = tid; i < (int)cnt; i += bd)
                loc += ((unsigned int)(sk[i] >> 32) >= mid);
            #pragma unroll
            for (int o = 16; o > 0; o >>= 1)
                loc += __shfl_down_sync(0xFFFFFFFFu, loc, o);
            if ((tid & 31) == 0 && loc) atomicAdd(&s_cnt, loc);
            __syncthreads();
            int cm = s_cnt;
            __syncthreads();
            if (cm < KTOP) hi = mid;
            else { lo = mid; if (cm <= SELCAP) break; }
        }
        if (tid == 0) s_thr = lo;
        __syncthreads();
    }

    // compact survivors (fkey >= T) into sel[]
    unsigned int T = s_thr;
    for (int i = tid; i < (int)cnt; i += bd) {
        unsigned long long k = sk[i];
        if ((unsigned int)(k >> 32) >= T) {
            int pos = atomicAdd(&s_sel, 1);
            if (pos < SELCAP) sel[pos] = k;
        }
    }
    __syncthreads();
    int nsel = s_sel; if (nsel > SELCAP) nsel = SELCAP;
    for (int i = tid; i < SELCAP; i += bd)
        if (i >= nsel) sel[i] = 0ULL;
    __syncthreads();

    // bitonic sort SELCAP keys descending
    for (int k = 2; k <= SELCAP; k <<= 1) {
        for (int j = k >> 1; j > 0; j >>= 1) {
            int i = tid;
            int ixj = i ^ j;
            if (ixj > i && i < SELCAP) {
                unsigned long long a = sel[i], b = sel[ixj];
                bool up = ((i & k) == 0);
                if (up ? (a < b) : (a > b)) { sel[i] = b; sel[ixj] = a; }
            }
            __syncthreads();
        }
    }

    for (int k = tid; k < KTOP; k += bd) {
        unsigned long long key = sel[k];
        g_topk_key[c * KTOP + k] = (unsigned int)(key >> 32);
        g_topk_idx[c * KTOP + k] = 65535 - (int)(key & 0xFFFFu);
    }
}

// 80-way merge of sorted class lists -> global top-100, then decode + write.
__global__ void merge_decode_kernel(const float* __restrict__ txty,
                                    const float* __restrict__ twth,
                                    float* __restrict__ out) {
    __shared__ unsigned int skey[NC * KTOP];   // 32 KB
    __shared__ int heads[NC];
    __shared__ int res[KTOP];                  // (cls<<16)|rank

    const int tid = threadIdx.x;
    for (int i = tid; i < NC * KTOP; i += blockDim.x) skey[i] = g_topk_key[i];
    if (tid < NC) heads[tid] = 0;
    __syncthreads();

    if (tid < 32) {
        for (int t = 0; t < KTOP; t++) {
            unsigned long long v = 0ULL;
            #pragma unroll
            for (int cc = 0; cc < 3; cc++) {
                int c = tid + cc * 32;
                if (c < NC) {
                    int h = heads[c];
                    if (h < KTOP)
                        v = max(v, ((unsigned long long)skey[c * KTOP + h] << 7)
                                 | (unsigned int)(NC - 1 - c));
                }
            }
            #pragma unroll
            for (int o = 16; o > 0; o >>= 1) {
                unsigned long long u = __shfl_xor_sync(0xFFFFFFFFu, v, o);
                if (u > v) v = u;
            }
            int w = NC - 1 - (int)(v & 127u);
            if (tid == 0) { res[t] = (w << 16) | heads[w]; heads[w]++; }
            __syncwarp();
        }
    }
    __syncthreads();

    if (tid < KTOP) {
        int r = res[tid];
        int cls = r >> 16, rank = r & 0xFFFF;
        int j = cls * KTOP + rank;
        int spatial = g_topk_idx[j];
        float logit = fkeyinv(skey[j]);
        float score = 1.0f / (1.0f + expf(-logit));

        int y = spatial >> 8, x = spatial & 255;
        float tx = txty[spatial];
        float ty = txty[HWSZ + spatial];
        float tw = twth[spatial];
        float th = twth[HWSZ + spatial];

        float cx = ((float)x + 1.0f / (1.0f + expf(-tx))) * 4.0f;
        float cy = ((float)y + 1.0f / (1.0f + expf(-ty))) * 4.0f;
        float w2 = expf(tw) * 2.0f;
        float h2 = expf(th) * 2.0f;
        const float inv = 1.0f / 1024.0f;

        out[tid * 4 + 0] = fminf(fmaxf((cx - w2) * inv, 0.0f), 1.0f);
        out[tid * 4 + 1] = fminf(fmaxf((cy - h2) * inv, 0.0f), 1.0f);
        out[tid * 4 + 2] = fminf(fmaxf((cx + w2) * inv, 0.0f), 1.0f);
        out[tid * 4 + 3] = fminf(fmaxf((cy + h2) * inv, 0.0f), 1.0f);
        out[4 * KTOP + tid] = score;
        out[5 * KTOP + tid] = (float)cls;
    }
}

extern "C" void kernel_launch(void* const* d_in, const int* in_sizes, int n_in,
                              void* d_out, int out_size) {
    const float* cls  = (const float*)d_in[0];
    const float* txty = (const float*)d_in[1];
    const float* twth = (const float*)d_in[2];
    float* out = (float*)d_out;

    const int smem_class = (MAXCAND + SELCAP) * sizeof(unsigned long long);
    cudaFuncSetAttribute(class_topk_kernel,
                         cudaFuncAttributeMaxDynamicSharedMemorySize, smem_class);

    zero_counts_kernel<<<1, 128>>>();
    dim3 grid(WW / 32, HH / 32, NC);
    dim3 blk(32, 32);
    suppress_kernel<<<grid, blk>>>(cls);
    class_topk_kernel<<<NC, 1024, smem_class>>>();
    merge_decode_kernel<<<1, 1024>>>(txty, twth, out);
}

// round 5
// speedup vs baseline: 1.7182x; 1.0071x over previous
#include <cuda_runtime.h>
#include <cstdint>

#define HH 256
#define WW 256
#define NC 80
#define HWSZ 65536
#define KTOP 100
#define MAXCAND 8192
#define SELCAP 1024

// scratch (no cudaMalloc allowed)
__device__ unsigned int        g_count[NC];
__device__ unsigned long long  g_cand[NC][MAXCAND];
__device__ unsigned int        g_topk_key[NC * KTOP];   // fkey(logit), sorted desc per class
__device__ int                 g_topk_idx[NC * KTOP];   // spatial index in [0,65536)

// monotone float->uint key (handles negatives)
__device__ __forceinline__ unsigned int fkey(float f) {
    unsigned int b = __float_as_uint(f);
    return b ^ ((b & 0x80000000u) ? 0xFFFFFFFFu : 0x80000000u);
}
__device__ __forceinline__ float fkeyinv(unsigned int k) {
    unsigned int b = k ^ ((k & 0x80000000u) ? 0x80000000u : 0xFFFFFFFFu);
    return __uint_as_float(b);
}

__global__ void zero_counts_kernel() {
    if (threadIdx.x < NC) g_count[threadIdx.x] = 0u;
}

// 5x5 strict-window max (SAME, -inf pad) on logits of batch 0; compact survivors.
__global__ void suppress_kernel(const float* __restrict__ cls) {
    __shared__ float t[36][36 + 1];
    __shared__ float rmax[36][32 + 1];
    const int c  = blockIdx.z;
    const int x0 = blockIdx.x * 32, y0 = blockIdx.y * 32;
    const float* p = cls + (size_t)c * HWSZ;   // batch 0
    const int tid = threadIdx.y * 32 + threadIdx.x;

    for (int i = tid; i < 36 * 36; i += 1024) {
        int ly = i / 36, lx = i % 36;
        int gy = y0 + ly - 2, gx = x0 + lx - 2;
        float v = -__int_as_float(0x7f800000);  // -inf
        if (gy >= 0 && gy < HH && gx >= 0 && gx < WW) v = p[gy * WW + gx];
        t[ly][lx] = v;
    }
    __syncthreads();
    for (int i = tid; i < 36 * 32; i += 1024) {
        int ly = i / 32, lx = i % 32;
        float m = t[ly][lx];
        m = fmaxf(m, t[ly][lx + 1]);
        m = fmaxf(m, t[ly][lx + 2]);
        m = fmaxf(m, t[ly][lx + 3]);
        m = fmaxf(m, t[ly][lx + 4]);
        rmax[ly][lx] = m;
    }
    __syncthreads();
    const int lx = threadIdx.x, ly = threadIdx.y;
    float v = t[ly + 2][lx + 2];
    float m = rmax[ly][lx];
    m = fmaxf(m, rmax[ly + 1][lx]);
    m = fmaxf(m, rmax[ly + 2][lx]);
    m = fmaxf(m, rmax[ly + 3][lx]);
    m = fmaxf(m, rmax[ly + 4][lx]);
    if (v == m) {
        int idx = (y0 + ly) * WW + (x0 + lx);
        unsigned int pos = atomicAdd(&g_count[c], 1u);
        if (pos < MAXCAND)
            g_cand[c][pos] = ((unsigned long long)fkey(v) << 32)
                           | (unsigned int)(65535 - idx);   // lower idx => bigger key tail
    }
}

// per-class top-100 via threshold quickselect + small bitonic sort.
// dynamic smem layout: [MAXCAND ull keys][SELCAP ull selected]
__global__ void class_topk_kernel() {
    extern __shared__ unsigned long long sk[];
    unsigned long long* sel = sk + MAXCAND;
    __shared__ int s_cnt;
    __shared__ int s_sel;
    __shared__ unsigned int s_thr;

    const int c   = blockIdx.x;
    const int tid = threadIdx.x;
    const int bd  = blockDim.x;

    unsigned int cnt = g_count[c];
    if (cnt > MAXCAND) cnt = MAXCAND;

    for (int i = tid; i < (int)cnt; i += bd) sk[i] = g_cand[c][i];
    if (tid == 0) { s_thr = 0u; s_sel = 0; }
    __syncthreads();

    // binary search on fkey threshold so that count(fkey >= T) in [KTOP, SELCAP]
    if (cnt > SELCAP) {
        unsigned int lo = 0u, hi = 0xFFFFFFFFu;
        for (int iter = 0; iter < 32; iter++) {
            if (hi - lo <= 1u) break;
            unsigned int mid = lo + ((hi - lo) >> 1);
            if (tid == 0) s_cnt = 0;
            __syncthreads();
            int loc = 0;
            for (int i = tid; i < (int)cnt; i += bd)
                loc += ((unsigned int)(sk[i] >> 32) >= mid);
            #pragma unroll
            for (int o = 16; o > 0; o >>= 1)
                loc += __shfl_down_sync(0xFFFFFFFFu, loc, o);
            if ((tid & 31) == 0 && loc) atomicAdd(&s_cnt, loc);
            __syncthreads();
            int cm = s_cnt;
            __syncthreads();
            if (cm < KTOP) hi = mid;
            else { lo = mid; if (cm <= SELCAP) break; }
        }
        if (tid == 0) s_thr = lo;
        __syncthreads();
    }

    // compact survivors (fkey >= T) into sel[]
    unsigned int T = s_thr;
    for (int i = tid; i < (int)cnt; i += bd) {
        unsigned long long k = sk[i];
        if ((unsigned int)(k >> 32) >= T) {
            int pos = atomicAdd(&s_sel, 1);
            if (pos < SELCAP) sel[pos] = k;
        }
    }
    __syncthreads();
    int nsel = s_sel; if (nsel > SELCAP) nsel = SELCAP;
    for (int i = tid; i < SELCAP; i += bd)
        if (i >= nsel) sel[i] = 0ULL;
    __syncthreads();

    // bitonic sort SELCAP keys descending
    for (int k = 2; k <= SELCAP; k <<= 1) {
        for (int j = k >> 1; j > 0; j >>= 1) {
            int i = tid;
            int ixj = i ^ j;
            if (ixj > i && i < SELCAP) {
                unsigned long long a = sel[i], b = sel[ixj];
                bool up = ((i & k) == 0);
                if (up ? (a < b) : (a > b)) { sel[i] = b; sel[ixj] = a; }
            }
            __syncthreads();
        }
    }

    for (int k = tid; k < KTOP; k += bd) {
        unsigned long long key = sel[k];
        g_topk_key[c * KTOP + k] = (unsigned int)(key >> 32);
        g_topk_idx[c * KTOP + k] = 65535 - (int)(key & 0xFFFFu);
    }
}

// 80-way merge of sorted class lists -> global top-100, then decode + write.
__global__ void merge_decode_kernel(const float* __restrict__ txty,
                                    const float* __restrict__ twth,
                                    float* __restrict__ out) {
    __shared__ unsigned int skey[NC * KTOP];   // 32 KB
    __shared__ int heads[NC];
    __shared__ int res[KTOP];                  // (cls<<16)|rank

    const int tid = threadIdx.x;
    for (int i = tid; i < NC * KTOP; i += blockDim.x) skey[i] = g_topk_key[i];
    if (tid < NC) heads[tid] = 0;
    __syncthreads();

    if (tid < 32) {
        for (int t = 0; t < KTOP; t++) {
            unsigned long long v = 0ULL;
            #pragma unroll
            for (int cc = 0; cc < 3; cc++) {
                int c = tid + cc * 32;
                if (c < NC) {
                    int h = heads[c];
                    if (h < KTOP)
                        v = max(v, ((unsigned long long)skey[c * KTOP + h] << 7)
                                 | (unsigned int)(NC - 1 - c));
                }
            }
            #pragma unroll
            for (int o = 16; o > 0; o >>= 1) {
                unsigned long long u = __shfl_xor_sync(0xFFFFFFFFu, v, o);
                if (u > v) v = u;
            }
            int w = NC - 1 - (int)(v & 127u);
            if (tid == 0) { res[t] = (w << 16) | heads[w]; heads[w]++; }
            __syncwarp();
        }
    }
    __syncthreads();

    if (tid < KTOP) {
        int r = res[tid];
        int cls = r >> 16, rank = r & 0xFFFF;
        int j = cls * KTOP + rank;
        int spatial = g_topk_idx[j];
        float logit = fkeyinv(skey[j]);
        float score = 1.0f / (1.0f + expf(-logit));

        int y = spatial >> 8, x = spatial & 255;
        float tx = txty[spatial];
        float ty = txty[HWSZ + spatial];
        float tw = twth[spatial];
        float th = twth[HWSZ + spatial];

        float cx = ((float)x + 1.0f / (1.0f + expf(-tx))) * 4.0f;
        float cy = ((float)y + 1.0f / (1.0f + expf(-ty))) * 4.0f;
        float w2 = expf(tw) * 2.0f;
        float h2 = expf(th) * 2.0f;
        const float inv = 1.0f / 1024.0f;

        out[tid * 4 + 0] = fminf(fmaxf((cx - w2) * inv, 0.0f), 1.0f);
        out[tid * 4 + 1] = fminf(fmaxf((cy - h2) * inv, 0.0f), 1.0f);
        out[tid * 4 + 2] = fminf(fmaxf((cx + w2) * inv, 0.0f), 1.0f);
        out[tid * 4 + 3] = fminf(fmaxf((cy + h2) * inv, 0.0f), 1.0f);
        out[4 * KTOP + tid] = score;
        out[5 * KTOP + tid] = (float)cls;
    }
}

extern "C" void kernel_launch(void* const* d_in, const int* in_sizes, int n_in,
                              void* d_out, int out_size) {
    const float* cls  = (const float*)d_in[0];
    const float* txty = (const float*)d_in[1];
    const float* twth = (const float*)d_in[2];
    float* out = (float*)d_out;

    const int smem_class = (MAXCAND + SELCAP) * sizeof(unsigned long long);
    cudaFuncSetAttribute(class_topk_kernel,
                         cudaFuncAttributeMaxDynamicSharedMemorySize, smem_class);

    zero_counts_kernel<<<1, 128>>>();
    dim3 grid(WW / 32, HH / 32, NC);
    dim3 blk(32, 32);
    suppress_kernel<<<grid, blk>>>(cls);
    class_topk_kernel<<<NC, 1024, smem_class>>>();
    merge_decode_kernel<<<1, 1024>>>(txty, twth, out);
}

// round 6
// speedup vs baseline: 1.8621x; 1.0838x over previous
#include <cuda_runtime.h>
#include <cstdint>

#define HH 256
#define WW 256
#define NC 80
#define HWSZ 65536
#define KTOP 100
#define MAXCAND 8192
#define NBKT 8192
#define CAP  1024

// scratch (no cudaMalloc allowed)
__device__ unsigned int        g_count[NC];          // zero-init at load; reset by class_topk
__device__ unsigned long long  g_cand[NC][MAXCAND];
__device__ unsigned int        g_topk_key[NC * KTOP];   // fkey(logit), sorted desc per class
__device__ int                 g_topk_idx[NC * KTOP];   // spatial index in [0,65536)

// monotone float->uint key (handles negatives)
__device__ __forceinline__ unsigned int fkey(float f) {
    unsigned int b = __float_as_uint(f);
    return b ^ ((b & 0x80000000u) ? 0xFFFFFFFFu : 0x80000000u);
}
__device__ __forceinline__ float fkeyinv(unsigned int k) {
    unsigned int b = k ^ ((k & 0x80000000u) ? 0x80000000u : 0xFFFFFFFFu);
    return __uint_as_float(b);
}

// 5x5 strict-window max (SAME, -inf pad) on logits of batch 0; compact survivors.
__global__ void suppress_kernel(const float* __restrict__ cls) {
    __shared__ float t[36][36 + 1];
    __shared__ float rmax[36][32 + 1];
    const int c  = blockIdx.z;
    const int x0 = blockIdx.x * 32, y0 = blockIdx.y * 32;
    const float* p = cls + (size_t)c * HWSZ;   // batch 0
    const int tid = threadIdx.y * 32 + threadIdx.x;

    for (int i = tid; i < 36 * 36; i += 1024) {
        int ly = i / 36, lx = i % 36;
        int gy = y0 + ly - 2, gx = x0 + lx - 2;
        float v = -__int_as_float(0x7f800000);  // -inf
        if (gy >= 0 && gy < HH && gx >= 0 && gx < WW) v = p[gy * WW + gx];
        t[ly][lx] = v;
    }
    __syncthreads();
    for (int i = tid; i < 36 * 32; i += 1024) {
        int ly = i / 32, lx = i % 32;
        float m = t[ly][lx];
        m = fmaxf(m, t[ly][lx + 1]);
        m = fmaxf(m, t[ly][lx + 2]);
        m = fmaxf(m, t[ly][lx + 3]);
        m = fmaxf(m, t[ly][lx + 4]);
        rmax[ly][lx] = m;
    }
    __syncthreads();
    const int lx = threadIdx.x, ly = threadIdx.y;
    float v = t[ly + 2][lx + 2];
    float m = rmax[ly][lx];
    m = fmaxf(m, rmax[ly + 1][lx]);
    m = fmaxf(m, rmax[ly + 2][lx]);
    m = fmaxf(m, rmax[ly + 3][lx]);
    m = fmaxf(m, rmax[ly + 4][lx]);
    if (v == m) {
        int idx = (y0 + ly) * WW + (x0 + lx);
        unsigned int pos = atomicAdd(&g_count[c], 1u);
        if (pos < MAXCAND)
            g_cand[c][pos] = ((unsigned long long)fkey(v) << 32)
                           | (unsigned int)(65535 - idx);   // lower idx => bigger key tail
    }
}

// Find smallest bucket B with suffix_count(>=B) >= need over hist[NBKT].
// Block-collective (1024 threads). Results in out3: {B, count_above_B, suffix(B)}.
__device__ void find_boundary(const unsigned int* hist, unsigned int* psums,
                              unsigned int* wsums, unsigned int need,
                              unsigned int* out3) {
    const int tid = threadIdx.x;
    unsigned int p = 0;
    const int base = tid * 8;
    #pragma unroll
    for (int k = 0; k < 8; k++) p += hist[base + k];
    unsigned int w = p;
    #pragma unroll
    for (int o = 16; o; o >>= 1) w += __shfl_down_sync(0xFFFFFFFFu, w, o);
    psums[tid] = p;
    if ((tid & 31) == 0) wsums[tid >> 5] = w;
    __syncthreads();
    if (tid == 0) {
        unsigned int acc = 0;
        int wstar = 0;
        for (int i = 31; i >= 0; i--) {
            if (acc + wsums[i] >= need || i == 0) { wstar = i; break; }
            acc += wsums[i];
        }
        int tstar = wstar * 32;
        for (int i = wstar * 32 + 31; i >= wstar * 32; i--) {
            if (acc + psums[i] >= need || i == wstar * 32) { tstar = i; break; }
            acc += psums[i];
        }
        unsigned int B = (unsigned int)(tstar * 8);
        for (int b = tstar * 8 + 7; b >= tstar * 8; b--) {
            if (acc + hist[b] >= need || b == tstar * 8) { B = (unsigned int)b; break; }
            acc += hist[b];
        }
        out3[0] = B;
        out3[1] = acc;
        out3[2] = acc + hist[B];
    }
    __syncthreads();
}

// per-class top-100: one-pass histogram select + small bitonic sort
__global__ void class_topk_kernel() {
    __shared__ unsigned int hist[NBKT];          // 32 KB
    __shared__ unsigned int psums[1024];         // 4 KB
    __shared__ unsigned int wsums[32];
    __shared__ unsigned int bout[3];
    __shared__ unsigned long long sel[CAP];      // 8 KB
    __shared__ int s_nsel;

    const int c   = blockIdx.x;
    const int tid = threadIdx.x;
    int cnt = (int)min(g_count[c], (unsigned int)MAXCAND);
    if (tid == 0) s_nsel = 0;
    __syncthreads();

    if (cnt > CAP) {
        for (int i = tid; i < NBKT; i += 1024) hist[i] = 0;
        __syncthreads();
        for (int i = tid; i < cnt; i += 1024) {
            unsigned int fk = (unsigned int)(g_cand[c][i] >> 32);
            atomicAdd(&hist[fk >> 19], 1u);
        }
        __syncthreads();
        find_boundary(hist, psums, wsums, KTOP, bout);
        unsigned int B1 = bout[0], above = bout[1], sfx = bout[2];
        unsigned int B2 = 0;
        bool two = false;
        if (sfx > CAP) {                          // refine within boundary bucket
            two = true;
            __syncthreads();
            for (int i = tid; i < NBKT; i += 1024) hist[i] = 0;
            __syncthreads();
            for (int i = tid; i < cnt; i += 1024) {
                unsigned int fk = (unsigned int)(g_cand[c][i] >> 32);
                if ((fk >> 19) == B1) atomicAdd(&hist[(fk >> 6) & 8191u], 1u);
            }
            __syncthreads();
            find_boundary(hist, psums, wsums, KTOP - above, bout);
            B2 = bout[0];
        }
        for (int i = tid; i < cnt; i += 1024) {
            unsigned long long key = g_cand[c][i];
            unsigned int fk = (unsigned int)(key >> 32);
            unsigned int b = fk >> 19;
            bool take = (b > B1) || (b == B1 && (!two || ((fk >> 6) & 8191u) >= B2));
            if (take) {
                int pos = atomicAdd(&s_nsel, 1);
                if (pos < CAP) sel[pos] = key;
            }
        }
    } else {
        for (int i = tid; i < cnt; i += 1024) sel[i] = g_cand[c][i];
        if (tid == 0) s_nsel = cnt;
    }
    __syncthreads();

    int nsel = min(s_nsel, CAP);
    int n = 128;
    while (n < nsel) n <<= 1;
    if (tid < n && tid >= nsel) sel[tid] = 0ULL;
    __syncthreads();

    // bitonic sort n keys descending (n <= 1024, one elem per thread)
    for (int k = 2; k <= n; k <<= 1) {
        for (int j = k >> 1; j > 0; j >>= 1) {
            if (tid < n) {
                int ixj = tid ^ j;
                if (ixj > tid) {
                    unsigned long long a = sel[tid], b = sel[ixj];
                    bool up = ((tid & k) == 0);
                    if (up ? (a < b) : (a > b)) { sel[tid] = b; sel[ixj] = a; }
                }
            }
            __syncthreads();
        }
    }

    if (tid < KTOP) {
        unsigned long long key = sel[tid];
        g_topk_key[c * KTOP + tid] = (unsigned int)(key >> 32);
        g_topk_idx[c * KTOP + tid] = 65535 - (int)(key & 0xFFFFull);
    }
    if (tid == 0) g_count[c] = 0;   // reset for next launch (determinism)
}

// global top-100 over 80*100 keys via histogram select, then decode + write
__global__ void global_topk_kernel(const float* __restrict__ txty,
                                   const float* __restrict__ twth,
                                   float* __restrict__ out) {
    __shared__ unsigned int hist[NBKT];
    __shared__ unsigned int psums[1024];
    __shared__ unsigned int wsums[32];
    __shared__ unsigned int bout[3];
    __shared__ unsigned long long sel[CAP];
    __shared__ int s_nsel;

    const int tid = threadIdx.x;
    const int N = NC * KTOP;   // 8000
    if (tid == 0) s_nsel = 0;

    for (int i = tid; i < NBKT; i += 1024) hist[i] = 0;
    __syncthreads();
    for (int i = tid; i < N; i += 1024)
        atomicAdd(&hist[g_topk_key[i] >> 19], 1u);
    __syncthreads();
    find_boundary(hist, psums, wsums, KTOP, bout);
    unsigned int B1 = bout[0], above = bout[1], sfx = bout[2];
    unsigned int B2 = 0;
    bool two = false;
    if (sfx > CAP) {
        two = true;
        __syncthreads();
        for (int i = tid; i < NBKT; i += 1024) hist[i] = 0;
        __syncthreads();
        for (int i = tid; i < N; i += 1024) {
            unsigned int fk = g_topk_key[i];
            if ((fk >> 19) == B1) atomicAdd(&hist[(fk >> 6) & 8191u], 1u);
        }
        __syncthreads();
        find_boundary(hist, psums, wsums, KTOP - above, bout);
        B2 = bout[0];
    }
    for (int i = tid; i < N; i += 1024) {
        unsigned int fk = g_topk_key[i];
        unsigned int b = fk >> 19;
        bool take = (b > B1) || (b == B1 && (!two || ((fk >> 6) & 8191u) >= B2));
        if (take) {
            int pos = atomicAdd(&s_nsel, 1);
            if (pos < CAP)
                sel[pos] = ((unsigned long long)fk << 13) | (unsigned int)(8191 - i);
        }
    }
    __syncthreads();

    int nsel = min(s_nsel, CAP);
    int n = 128;
    while (n < nsel) n <<= 1;
    if (tid < n && tid >= nsel) sel[tid] = 0ULL;
    __syncthreads();

    for (int k = 2; k <= n; k <<= 1) {
        for (int j = k >> 1; j > 0; j >>= 1) {
            if (tid < n) {
                int ixj = tid ^ j;
                if (ixj > tid) {
                    unsigned long long a = sel[tid], b = sel[ixj];
                    bool up = ((tid & k) == 0);
                    if (up ? (a < b) : (a > b)) { sel[tid] = b; sel[ixj] = a; }
                }
            }
            __syncthreads();
        }
    }

    if (tid < KTOP) {
        unsigned long long key = sel[tid];
        unsigned int fk = (unsigned int)(key >> 13);
        int flat = 8191 - (int)(key & 8191ull);
        int cls = flat / KTOP;
        int spatial = g_topk_idx[flat];
        float logit = fkeyinv(fk);
        float score = 1.0f / (1.0f + expf(-logit));

        int y = spatial >> 8, x = spatial & 255;
        float tx = txty[spatial];
        float ty = txty[HWSZ + spatial];
        float tw = twth[spatial];
        float th = twth[HWSZ + spatial];

        float cx = ((float)x + 1.0f / (1.0f + expf(-tx))) * 4.0f;
        float cy = ((float)y + 1.0f / (1.0f + expf(-ty))) * 4.0f;
        float w2 = expf(tw) * 2.0f;
        float h2 = expf(th) * 2.0f;
        const float inv = 1.0f / 1024.0f;

        out[tid * 4 + 0] = fminf(fmaxf((cx - w2) * inv, 0.0f), 1.0f);
        out[tid * 4 + 1] = fminf(fmaxf((cy - h2) * inv, 0.0f), 1.0f);
        out[tid * 4 + 2] = fminf(fmaxf((cx + w2) * inv, 0.0f), 1.0f);
        out[tid * 4 + 3] = fminf(fmaxf((cy + h2) * inv, 0.0f), 1.0f);
        out[4 * KTOP + tid] = score;
        out[5 * KTOP + tid] = (float)cls;
    }
}

extern "C" void kernel_launch(void* const* d_in, const int* in_sizes, int n_in,
                              void* d_out, int out_size) {
    const float* cls  = (const float*)d_in[0];
    const float* txty = (const float*)d_in[1];
    const float* twth = (const float*)d_in[2];
    float* out = (float*)d_out;

    dim3 grid(WW / 32, HH / 32, NC);
    dim3 blk(32, 32);
    suppress_kernel<<<grid, blk>>>(cls);
    class_topk_kernel<<<NC, 1024>>>();
    global_topk_kernel<<<1, 1024>>>(txty, twth, out);
}

// round 7
// speedup vs baseline: 2.6067x; 1.3999x over previous
#include <cuda_runtime.h>
#include <cstdint>

#define HH 256
#define WW 256
#define NC 80
#define HWSZ 65536
#define KTOP 100
#define MAXCAND 8192
#define NBKT 8192
#define CAP  1024
#define BAND 32
#define HALO 2
#define ROWS_LD (BAND + 2 * HALO)   // 36

// scratch (no cudaMalloc allowed)
__device__ unsigned int        g_count[NC];          // zero-init at load; reset by class_topk
__device__ unsigned long long  g_cand[NC][MAXCAND];
__device__ unsigned int        g_topk_key[NC * KTOP];   // fkey(logit), sorted desc per class
__device__ int                 g_topk_idx[NC * KTOP];   // spatial index in [0,65536)

// monotone float->uint key (handles negatives)
__device__ __forceinline__ unsigned int fkey(float f) {
    unsigned int b = __float_as_uint(f);
    return b ^ ((b & 0x80000000u) ? 0xFFFFFFFFu : 0x80000000u);
}
__device__ __forceinline__ float fkeyinv(unsigned int k) {
    unsigned int b = k ^ ((k & 0x80000000u) ? 0x80000000u : 0xFFFFFFFFu);
    return __uint_as_float(b);
}

// 5x5 strict-window max on logits of batch 0; separable, register-resident.
// grid: (HH/BAND, NC), block: 256 threads (one per column)
__global__ __launch_bounds__(256) void suppress_kernel(const float* __restrict__ cls) {
    __shared__ float sm[BAND][WW + 2 * HALO + 1];   // vertical maxima + -inf halo
    const int c  = blockIdx.y;
    const int y0 = blockIdx.x * BAND;
    const int x  = threadIdx.x;
    const int lane = x & 31;
    const float NEG = __int_as_float(0xff800000);
    const float* p = cls + (size_t)c * HWSZ;        // batch 0

    // load 36 rows of this column into registers (coalesced per row)
    float v[ROWS_LD];
    #pragma unroll
    for (int r = 0; r < ROWS_LD; r++) {
        int gy = y0 + r - HALO;
        v[r] = (gy >= 0 && gy < HH) ? p[(gy << 8) | x] : NEG;
    }

    // -inf halo columns (2 on each side)
    if (x < 2 * HALO) {
        int col = (x < HALO) ? x : (WW + x);        // 0,1, 258,259
        #pragma unroll
        for (int r = 0; r < BAND; r++) sm[r][col] = NEG;
    }

    // vertical max-5 -> smem (shifted by HALO)
    #pragma unroll
    for (int r = 0; r < BAND; r++) {
        float m = fmaxf(fmaxf(fmaxf(v[r], v[r + 1]), fmaxf(v[r + 2], v[r + 3])), v[r + 4]);
        sm[r][x + HALO] = m;
    }
    __syncthreads();

    // horizontal max-5, peak test, warp-aggregated emit
    #pragma unroll 4
    for (int r = 0; r < BAND; r++) {
        float h = fmaxf(fmaxf(fmaxf(sm[r][x], sm[r][x + 1]),
                              fmaxf(sm[r][x + 2], sm[r][x + 3])), sm[r][x + 4]);
        float center = v[r + HALO];
        bool take = (center == h);
        unsigned int mask = __ballot_sync(0xFFFFFFFFu, take);
        if (mask) {
            int nsur = __popc(mask);
            unsigned int pos = 0;
            if (lane == __ffs(mask) - 1) pos = atomicAdd(&g_count[c], (unsigned int)nsur);
            pos = __shfl_sync(0xFFFFFFFFu, pos, __ffs(mask) - 1);
            if (take) {
                unsigned int my = pos + __popc(mask & ((1u << lane) - 1));
                int idx = ((y0 + r) << 8) | x;
                if (my < MAXCAND)
                    g_cand[c][my] = ((unsigned long long)fkey(center) << 32)
                                  | (unsigned int)(65535 - idx);  // lower idx => bigger tail
            }
        }
    }
}

// Find smallest bucket B with suffix_count(>=B) >= need over hist[NBKT].
// Block-collective (1024 threads). Results in out3: {B, count_above_B, suffix(B)}.
__device__ void find_boundary(const unsigned int* hist, unsigned int* psums,
                              unsigned int* wsums, unsigned int need,
                              unsigned int* out3) {
    const int tid = threadIdx.x;
    unsigned int p = 0;
    const int base = tid * 8;
    #pragma unroll
    for (int k = 0; k < 8; k++) p += hist[base + k];
    unsigned int w = p;
    #pragma unroll
    for (int o = 16; o; o >>= 1) w += __shfl_down_sync(0xFFFFFFFFu, w, o);
    psums[tid] = p;
    if ((tid & 31) == 0) wsums[tid >> 5] = w;
    __syncthreads();
    if (tid == 0) {
        unsigned int acc = 0;
        int wstar = 0;
        for (int i = 31; i >= 0; i--) {
            if (acc + wsums[i] >= need || i == 0) { wstar = i; break; }
            acc += wsums[i];
        }
        int tstar = wstar * 32;
        for (int i = wstar * 32 + 31; i >= wstar * 32; i--) {
            if (acc + psums[i] >= need || i == wstar * 32) { tstar = i; break; }
            acc += psums[i];
        }
        unsigned int B = (unsigned int)(tstar * 8);
        for (int b = tstar * 8 + 7; b >= tstar * 8; b--) {
            if (acc + hist[b] >= need || b == tstar * 8) { B = (unsigned int)b; break; }
            acc += hist[b];
        }
        out3[0] = B;
        out3[1] = acc;
        out3[2] = acc + hist[B];
    }
    __syncthreads();
}

// per-class top-100: one-pass histogram select + small bitonic sort
__global__ void class_topk_kernel() {
    __shared__ unsigned int hist[NBKT];          // 32 KB
    __shared__ unsigned int psums[1024];         // 4 KB
    __shared__ unsigned int wsums[32];
    __shared__ unsigned int bout[3];
    __shared__ unsigned long long sel[CAP];      // 8 KB
    __shared__ int s_nsel;

    const int c   = blockIdx.x;
    const int tid = threadIdx.x;
    int cnt = (int)min(g_count[c], (unsigned int)MAXCAND);
    if (tid == 0) s_nsel = 0;
    __syncthreads();

    if (cnt > CAP) {
        for (int i = tid; i < NBKT; i += 1024) hist[i] = 0;
        __syncthreads();
        for (int i = tid; i < cnt; i += 1024) {
            unsigned int fk = (unsigned int)(g_cand[c][i] >> 32);
            atomicAdd(&hist[fk >> 19], 1u);
        }
        __syncthreads();
        find_boundary(hist, psums, wsums, KTOP, bout);
        unsigned int B1 = bout[0], above = bout[1], sfx = bout[2];
        unsigned int B2 = 0;
        bool two = false;
        if (sfx > CAP) {                          // refine within boundary bucket
            two = true;
            __syncthreads();
            for (int i = tid; i < NBKT; i += 1024) hist[i] = 0;
            __syncthreads();
            for (int i = tid; i < cnt; i += 1024) {
                unsigned int fk = (unsigned int)(g_cand[c][i] >> 32);
                if ((fk >> 19) == B1) atomicAdd(&hist[(fk >> 6) & 8191u], 1u);
            }
            __syncthreads();
            find_boundary(hist, psums, wsums, KTOP - above, bout);
            B2 = bout[0];
        }
        for (int i = tid; i < cnt; i += 1024) {
            unsigned long long key = g_cand[c][i];
            unsigned int fk = (unsigned int)(key >> 32);
            unsigned int b = fk >> 19;
            bool take = (b > B1) || (b == B1 && (!two || ((fk >> 6) & 8191u) >= B2));
            if (take) {
                int pos = atomicAdd(&s_nsel, 1);
                if (pos < CAP) sel[pos] = key;
            }
        }
    } else {
        for (int i = tid; i < cnt; i += 1024) sel[i] = g_cand[c][i];
        if (tid == 0) s_nsel = cnt;
    }
    __syncthreads();

    int nsel = min(s_nsel, CAP);
    int n = 128;
    while (n < nsel) n <<= 1;
    if (tid < n && tid >= nsel) sel[tid] = 0ULL;
    __syncthreads();

    // bitonic sort n keys descending (n <= 1024, one elem per thread)
    for (int k = 2; k <= n; k <<= 1) {
        for (int j = k >> 1; j > 0; j >>= 1) {
            if (tid < n) {
                int ixj = tid ^ j;
                if (ixj > tid) {
                    unsigned long long a = sel[tid], b = sel[ixj];
                    bool up = ((tid & k) == 0);
                    if (up ? (a < b) : (a > b)) { sel[tid] = b; sel[ixj] = a; }
                }
            }
            __syncthreads();
        }
    }

    if (tid < KTOP) {
        unsigned long long key = sel[tid];
        g_topk_key[c * KTOP + tid] = (unsigned int)(key >> 32);
        g_topk_idx[c * KTOP + tid] = 65535 - (int)(key & 0xFFFFull);
    }
    if (tid == 0) g_count[c] = 0;   // reset for next launch (determinism)
}

// global top-100 over 80*100 keys via histogram select, then decode + write
__global__ void global_topk_kernel(const float* __restrict__ txty,
                                   const float* __restrict__ twth,
                                   float* __restrict__ out) {
    __shared__ unsigned int hist[NBKT];
    __shared__ unsigned int psums[1024];
    __shared__ unsigned int wsums[32];
    __shared__ unsigned int bout[3];
    __shared__ unsigned long long sel[CAP];
    __shared__ int s_nsel;

    const int tid = threadIdx.x;
    const int N = NC * KTOP;   // 8000
    if (tid == 0) s_nsel = 0;

    for (int i = tid; i < NBKT; i += 1024) hist[i] = 0;
    __syncthreads();
    for (int i = tid; i < N; i += 1024)
        atomicAdd(&hist[g_topk_key[i] >> 19], 1u);
    __syncthreads();
    find_boundary(hist, psums, wsums, KTOP, bout);
    unsigned int B1 = bout[0], above = bout[1], sfx = bout[2];
    unsigned int B2 = 0;
    bool two = false;
    if (sfx > CAP) {
        two = true;
        __syncthreads();
        for (int i = tid; i < NBKT; i += 1024) hist[i] = 0;
        __syncthreads();
        for (int i = tid; i < N; i += 1024) {
            unsigned int fk = g_topk_key[i];
            if ((fk >> 19) == B1) atomicAdd(&hist[(fk >> 6) & 8191u], 1u);
        }
        __syncthreads();
        find_boundary(hist, psums, wsums, KTOP - above, bout);
        B2 = bout[0];
    }
    for (int i = tid; i < N; i += 1024) {
        unsigned int fk = g_topk_key[i];
        unsigned int b = fk >> 19;
        bool take = (b > B1) || (b == B1 && (!two || ((fk >> 6) & 8191u) >= B2));
        if (take) {
            int pos = atomicAdd(&s_nsel, 1);
            if (pos < CAP)
                sel[pos] = ((unsigned long long)fk << 13) | (unsigned int)(8191 - i);
        }
    }
    __syncthreads();

    int nsel = min(s_nsel, CAP);
    int n = 128;
    while (n < nsel) n <<= 1;
    if (tid < n && tid >= nsel) sel[tid] = 0ULL;
    __syncthreads();

    for (int k = 2; k <= n; k <<= 1) {
        for (int j = k >> 1; j > 0; j >>= 1) {
            if (tid < n) {
                int ixj = tid ^ j;
                if (ixj > tid) {
                    unsigned long long a = sel[tid], b = sel[ixj];
                    bool up = ((tid & k) == 0);
                    if (up ? (a < b) : (a > b)) { sel[tid] = b; sel[ixj] = a; }
                }
            }
            __syncthreads();
        }
    }

    if (tid < KTOP) {
        unsigned long long key = sel[tid];
        unsigned int fk = (unsigned int)(key >> 13);
        int flat = 8191 - (int)(key & 8191ull);
        int cls = flat / KTOP;
        int spatial = g_topk_idx[flat];
        float logit = fkeyinv(fk);
        float score = 1.0f / (1.0f + expf(-logit));

        int y = spatial >> 8, x = spatial & 255;
        float tx = txty[spatial];
        float ty = txty[HWSZ + spatial];
        float tw = twth[spatial];
        float th = twth[HWSZ + spatial];

        float cx = ((float)x + 1.0f / (1.0f + expf(-tx))) * 4.0f;
        float cy = ((float)y + 1.0f / (1.0f + expf(-ty))) * 4.0f;
        float w2 = expf(tw) * 2.0f;
        float h2 = expf(th) * 2.0f;
        const float inv = 1.0f / 1024.0f;

        out[tid * 4 + 0] = fminf(fmaxf((cx - w2) * inv, 0.0f), 1.0f);
        out[tid * 4 + 1] = fminf(fmaxf((cy - h2) * inv, 0.0f), 1.0f);
        out[tid * 4 + 2] = fminf(fmaxf((cx + w2) * inv, 0.0f), 1.0f);
        out[tid * 4 + 3] = fminf(fmaxf((cy + h2) * inv, 0.0f), 1.0f);
        out[4 * KTOP + tid] = score;
        out[5 * KTOP + tid] = (float)cls;
    }
}

extern "C" void kernel_launch(void* const* d_in, const int* in_sizes, int n_in,
                              void* d_out, int out_size) {
    const float* cls  = (const float*)d_in[0];
    const float* txty = (const float*)d_in[1];
    const float* twth = (const float*)d_in[2];
    float* out = (float*)d_out;

    dim3 grid(HH / BAND, NC);
    suppress_kernel<<<grid, 256>>>(cls);
    class_topk_kernel<<<NC, 1024>>>();
    global_topk_kernel<<<1, 1024>>>(txty, twth, out);
}

// round 8
// speedup vs baseline: 2.7167x; 1.0422x over previous
#include <cuda_runtime.h>
#include <cstdint>

#define HH 256
#define WW 256
#define NC 80
#define HWSZ 65536
#define KTOP 100
#define MAXCAND 8192
#define NBKT 8192
#define CAP  1024
#define BAND 32
#define HALF 16
#define HALO 2
#define ROWS_H (HALF + 2 * HALO)   // 20 rows loaded per half-band

// scratch (no cudaMalloc allowed)
__device__ unsigned int        g_count[NC];          // zero-init at load; reset by class_topk
__device__ unsigned long long  g_cand[NC][MAXCAND];
__device__ unsigned int        g_topk_key[NC * KTOP];   // fkey(logit), sorted desc per class
__device__ int                 g_topk_idx[NC * KTOP];   // spatial index in [0,65536)

// monotone float->uint key (handles negatives)
__device__ __forceinline__ unsigned int fkey(float f) {
    unsigned int b = __float_as_uint(f);
    return b ^ ((b & 0x80000000u) ? 0xFFFFFFFFu : 0x80000000u);
}
__device__ __forceinline__ float fkeyinv(unsigned int k) {
    unsigned int b = k ^ ((k & 0x80000000u) ? 0x80000000u : 0xFFFFFFFFu);
    return __uint_as_float(b);
}

// 5x5 strict-window max on logits of batch 0; separable, register-resident,
// processed as two 16-row half-bands to keep the live load set at 20 regs
// (lets ptxas front-batch all 20 LDGs -> MLP ~20 per thread).
// grid: (HH/BAND, NC), block: 256 threads (one per column)
__global__ __launch_bounds__(256, 4) void suppress_kernel(const float* __restrict__ cls) {
    __shared__ float sm[HALF][WW + 2 * HALO + 1];   // vertical maxima + -inf col halo
    const int c  = blockIdx.y;
    const int y0 = blockIdx.x * BAND;
    const int x  = threadIdx.x;
    const int lane = x & 31;
    const float NEG = __int_as_float(0xff800000);
    const float* p = cls + (size_t)c * HWSZ;        // batch 0

    // -inf halo columns (2 each side), written once
    if (x < 2 * HALO) {
        int col = (x < HALO) ? x : (WW + x);        // 0,1, 258,259
        #pragma unroll
        for (int r = 0; r < HALF; r++) sm[r][col] = NEG;
    }

    #pragma unroll
    for (int h = 0; h < 2; h++) {
        const int yb = y0 + h * HALF;               // first output row of this half

        // 20 independent loads into registers (coalesced 128B per warp-row)
        float v[ROWS_H];
        #pragma unroll
        for (int r = 0; r < ROWS_H; r++) {
            int gy = yb + r - HALO;
            v[r] = (gy >= 0 && gy < HH) ? p[(gy << 8) | x] : NEG;
        }

        // vertical max-5 -> smem
        #pragma unroll
        for (int r = 0; r < HALF; r++) {
            float m = fmaxf(fmaxf(fmaxf(v[r], v[r + 1]),
                                  fmaxf(v[r + 2], v[r + 3])), v[r + 4]);
            sm[r][x + HALO] = m;
        }
        __syncthreads();

        // horizontal max-5, peak test, warp-aggregated emit
        #pragma unroll 4
        for (int r = 0; r < HALF; r++) {
            float hm = fmaxf(fmaxf(fmaxf(sm[r][x], sm[r][x + 1]),
                                   fmaxf(sm[r][x + 2], sm[r][x + 3])), sm[r][x + 4]);
            float center = v[r + HALO];
            bool take = (center == hm);
            unsigned int mask = __ballot_sync(0xFFFFFFFFu, take);
            if (mask) {
                int leader = __ffs(mask) - 1;
                unsigned int pos = 0;
                if (lane == leader)
                    pos = atomicAdd(&g_count[c], (unsigned int)__popc(mask));
                pos = __shfl_sync(0xFFFFFFFFu, pos, leader);
                if (take) {
                    unsigned int my = pos + __popc(mask & ((1u << lane) - 1));
                    int idx = ((yb + r) << 8) | x;
                    if (my < MAXCAND)
                        g_cand[c][my] = ((unsigned long long)fkey(center) << 32)
                                      | (unsigned int)(65535 - idx); // lower idx => bigger tail
                }
            }
        }
        __syncthreads();   // before next half overwrites sm
    }
}

// Find smallest bucket B with suffix_count(>=B) >= need over hist[NBKT].
// Block-collective (1024 threads). Results in out3: {B, count_above_B, suffix(B)}.
__device__ void find_boundary(const unsigned int* hist, unsigned int* psums,
                              unsigned int* wsums, unsigned int need,
                              unsigned int* out3) {
    const int tid = threadIdx.x;
    unsigned int p = 0;
    const int base = tid * 8;
    #pragma unroll
    for (int k = 0; k < 8; k++) p += hist[base + k];
    unsigned int w = p;
    #pragma unroll
    for (int o = 16; o; o >>= 1) w += __shfl_down_sync(0xFFFFFFFFu, w, o);
    psums[tid] = p;
    if ((tid & 31) == 0) wsums[tid >> 5] = w;
    __syncthreads();
    if (tid == 0) {
        unsigned int acc = 0;
        int wstar = 0;
        for (int i = 31; i >= 0; i--) {
            if (acc + wsums[i] >= need || i == 0) { wstar = i; break; }
            acc += wsums[i];
        }
        int tstar = wstar * 32;
        for (int i = wstar * 32 + 31; i >= wstar * 32; i--) {
            if (acc + psums[i] >= need || i == wstar * 32) { tstar = i; break; }
            acc += psums[i];
        }
        unsigned int B = (unsigned int)(tstar * 8);
        for (int b = tstar * 8 + 7; b >= tstar * 8; b--) {
            if (acc + hist[b] >= need || b == tstar * 8) { B = (unsigned int)b; break; }
            acc += hist[b];
        }
        out3[0] = B;
        out3[1] = acc;
        out3[2] = acc + hist[B];
    }
    __syncthreads();
}

// per-class top-100: one-pass histogram select + small bitonic sort
__global__ void class_topk_kernel() {
    __shared__ unsigned int hist[NBKT];          // 32 KB
    __shared__ unsigned int psums[1024];         // 4 KB
    __shared__ unsigned int wsums[32];
    __shared__ unsigned int bout[3];
    __shared__ unsigned long long sel[CAP];      // 8 KB
    __shared__ int s_nsel;

    const int c   = blockIdx.x;
    const int tid = threadIdx.x;
    int cnt = (int)min(g_count[c], (unsigned int)MAXCAND);
    if (tid == 0) s_nsel = 0;
    __syncthreads();

    if (cnt > CAP) {
        for (int i = tid; i < NBKT; i += 1024) hist[i] = 0;
        __syncthreads();
        for (int i = tid; i < cnt; i += 1024) {
            unsigned int fk = (unsigned int)(g_cand[c][i] >> 32);
            atomicAdd(&hist[fk >> 19], 1u);
        }
        __syncthreads();
        find_boundary(hist, psums, wsums, KTOP, bout);
        unsigned int B1 = bout[0], above = bout[1], sfx = bout[2];
        unsigned int B2 = 0;
        bool two = false;
        if (sfx > CAP) {                          // refine within boundary bucket
            two = true;
            __syncthreads();
            for (int i = tid; i < NBKT; i += 1024) hist[i] = 0;
            __syncthreads();
            for (int i = tid; i < cnt; i += 1024) {
                unsigned int fk = (unsigned int)(g_cand[c][i] >> 32);
                if ((fk >> 19) == B1) atomicAdd(&hist[(fk >> 6) & 8191u], 1u);
            }
            __syncthreads();
            find_boundary(hist, psums, wsums, KTOP - above, bout);
            B2 = bout[0];
        }
        for (int i = tid; i < cnt; i += 1024) {
            unsigned long long key = g_cand[c][i];
            unsigned int fk = (unsigned int)(key >> 32);
            unsigned int b = fk >> 19;
            bool take = (b > B1) || (b == B1 && (!two || ((fk >> 6) & 8191u) >= B2));
            if (take) {
                int pos = atomicAdd(&s_nsel, 1);
                if (pos < CAP) sel[pos] = key;
            }
        }
    } else {
        for (int i = tid; i < cnt; i += 1024) sel[i] = g_cand[c][i];
        if (tid == 0) s_nsel = cnt;
    }
    __syncthreads();

    int nsel = min(s_nsel, CAP);
    int n = 128;
    while (n < nsel) n <<= 1;
    if (tid < n && tid >= nsel) sel[tid] = 0ULL;
    __syncthreads();

    // bitonic sort n keys descending (n <= 1024, one elem per thread)
    for (int k = 2; k <= n; k <<= 1) {
        for (int j = k >> 1; j > 0; j >>= 1) {
            if (tid < n) {
                int ixj = tid ^ j;
                if (ixj > tid) {
                    unsigned long long a = sel[tid], b = sel[ixj];
                    bool up = ((tid & k) == 0);
                    if (up ? (a < b) : (a > b)) { sel[tid] = b; sel[ixj] = a; }
                }
            }
            __syncthreads();
        }
    }

    if (tid < KTOP) {
        unsigned long long key = sel[tid];
        g_topk_key[c * KTOP + tid] = (unsigned int)(key >> 32);
        g_topk_idx[c * KTOP + tid] = 65535 - (int)(key & 0xFFFFull);
    }
    if (tid == 0) g_count[c] = 0;   // reset for next launch (determinism)
}

// global top-100 over 80*100 keys via histogram select, then decode + write
__global__ void global_topk_kernel(const float* __restrict__ txty,
                                   const float* __restrict__ twth,
                                   float* __restrict__ out) {
    __shared__ unsigned int hist[NBKT];
    __shared__ unsigned int psums[1024];
    __shared__ unsigned int wsums[32];
    __shared__ unsigned int bout[3];
    __shared__ unsigned long long sel[CAP];
    __shared__ int s_nsel;

    const int tid = threadIdx.x;
    const int N = NC * KTOP;   // 8000
    if (tid == 0) s_nsel = 0;

    for (int i = tid; i < NBKT; i += 1024) hist[i] = 0;
    __syncthreads();
    for (int i = tid; i < N; i += 1024)
        atomicAdd(&hist[g_topk_key[i] >> 19], 1u);
    __syncthreads();
    find_boundary(hist, psums, wsums, KTOP, bout);
    unsigned int B1 = bout[0], above = bout[1], sfx = bout[2];
    unsigned int B2 = 0;
    bool two = false;
    if (sfx > CAP) {
        two = true;
        __syncthreads();
        for (int i = tid; i < NBKT; i += 1024) hist[i] = 0;
        __syncthreads();
        for (int i = tid; i < N; i += 1024) {
            unsigned int fk = g_topk_key[i];
            if ((fk >> 19) == B1) atomicAdd(&hist[(fk >> 6) & 8191u], 1u);
        }
        __syncthreads();
        find_boundary(hist, psums, wsums, KTOP - above, bout);
        B2 = bout[0];
    }
    for (int i = tid; i < N; i += 1024) {
        unsigned int fk = g_topk_key[i];
        unsigned int b = fk >> 19;
        bool take = (b > B1) || (b == B1 && (!two || ((fk >> 6) & 8191u) >= B2));
        if (take) {
            int pos = atomicAdd(&s_nsel, 1);
            if (pos < CAP)
                sel[pos] = ((unsigned long long)fk << 13) | (unsigned int)(8191 - i);
        }
    }
    __syncthreads();

    int nsel = min(s_nsel, CAP);
    int n = 128;
    while (n < nsel) n <<= 1;
    if (tid < n && tid >= nsel) sel[tid] = 0ULL;
    __syncthreads();

    for (int k = 2; k <= n; k <<= 1) {
        for (int j = k >> 1; j > 0; j >>= 1) {
            if (tid < n) {
                int ixj = tid ^ j;
                if (ixj > tid) {
                    unsigned long long a = sel[tid], b = sel[ixj];
                    bool up = ((tid & k) == 0);
                    if (up ? (a < b) : (a > b)) { sel[tid] = b; sel[ixj] = a; }
                }
            }
            __syncthreads();
        }
    }

    if (tid < KTOP) {
        unsigned long long key = sel[tid];
        unsigned int fk = (unsigned int)(key >> 13);
        int flat = 8191 - (int)(key & 8191ull);
        int cls = flat / KTOP;
        int spatial = g_topk_idx[flat];
        float logit = fkeyinv(fk);
        float score = 1.0f / (1.0f + expf(-logit));

        int y = spatial >> 8, x = spatial & 255;
        float tx = txty[spatial];
        float ty = txty[HWSZ + spatial];
        float tw = twth[spatial];
        float th = twth[HWSZ + spatial];

        float cx = ((float)x + 1.0f / (1.0f + expf(-tx))) * 4.0f;
        float cy = ((float)y + 1.0f / (1.0f + expf(-ty))) * 4.0f;
        float w2 = expf(tw) * 2.0f;
        float h2 = expf(th) * 2.0f;
        const float inv = 1.0f / 1024.0f;

        out[tid * 4 + 0] = fminf(fmaxf((cx - w2) * inv, 0.0f), 1.0f);
        out[tid * 4 + 1] = fminf(fmaxf((cy - h2) * inv, 0.0f), 1.0f);
        out[tid * 4 + 2] = fminf(fmaxf((cx + w2) * inv, 0.0f), 1.0f);
        out[tid * 4 + 3] = fminf(fmaxf((cy + h2) * inv, 0.0f), 1.0f);
        out[4 * KTOP + tid] = score;
        out[5 * KTOP + tid] = (float)cls;
    }
}

extern "C" void kernel_launch(void* const* d_in, const int* in_sizes, int n_in,
                              void* d_out, int out_size) {
    const float* cls  = (const float*)d_in[0];
    const float* txty = (const float*)d_in[1];
    const float* twth = (const float*)d_in[2];
    float* out = (float*)d_out;

    dim3 grid(HH / BAND, NC);
    suppress_kernel<<<grid, 256>>>(cls);
    class_topk_kernel<<<NC, 1024>>>();
    global_topk_kernel<<<1, 1024>>>(txty, twth, out);
}

// round 9
// speedup vs baseline: 4.8588x; 1.7885x over previous
#include <cuda_runtime.h>
#include <cstdint>

#define HH 256
#define WW 256
#define NC 80
#define HWSZ 65536
#define KTOP 100
#define MAXCAND 8192
#define NBKT 8192
#define CAP  1024
#define BAND 32

// scratch (no cudaMalloc allowed)
__device__ unsigned int        g_count[NC];          // zero-init at load; reset by class_topk
__device__ unsigned long long  g_cand[NC][MAXCAND];
__device__ unsigned int        g_topk_key[NC * KTOP];   // fkey(logit), sorted desc per class
__device__ int                 g_topk_idx[NC * KTOP];   // spatial index in [0,65536)

// monotone float->uint key (handles negatives)
__device__ __forceinline__ unsigned int fkey(float f) {
    unsigned int b = __float_as_uint(f);
    return b ^ ((b & 0x80000000u) ? 0xFFFFFFFFu : 0x80000000u);
}
__device__ __forceinline__ float fkeyinv(unsigned int k) {
    unsigned int b = k ^ ((k & 0x80000000u) ? 0x80000000u : 0xFFFFFFFFu);
    return __uint_as_float(b);
}
__device__ __forceinline__ float4 f4max(float4 a, float4 b) {
    return make_float4(fmaxf(a.x, b.x), fmaxf(a.y, b.y),
                       fmaxf(a.z, b.z), fmaxf(a.w, b.w));
}

// 5x5 strict-window max on logits of batch 0.
// Block = 256 threads: tx = tid&63 (float4 column group), ty = tid>>6 (8-row group).
// Each thread: 12 float4 LDG (batched, 48 regs) -> 8 vm rows -> smem -> horizontal.
// grid: (HH/BAND, NC)
__global__ __launch_bounds__(256, 3) void suppress_kernel(const float* __restrict__ cls) {
    __shared__ float smvm[BAND][WW + 8];            // vm + 4-col -inf halo each side
    const int c   = blockIdx.y;
    const int y0  = blockIdx.x * BAND;
    const int tid = threadIdx.x;
    const int tx  = tid & 63;
    const int ty  = tid >> 6;
    const int lane = tid & 31;
    const float NEG = __int_as_float(0xff800000);
    const float4 NEG4 = make_float4(NEG, NEG, NEG, NEG);
    const float4* __restrict__ p4 =
        reinterpret_cast<const float4*>(cls) + ((size_t)c << 14);   // batch 0, class c

    // 12 independent 128-bit loads (rows ty*8-2 .. ty*8+9)
    float4 v[12];
    const int ybase = y0 + ty * 8 - 2;
    #pragma unroll
    for (int r = 0; r < 12; r++) {
        int gy = ybase + r;
        v[r] = (gy >= 0 && gy < HH) ? p4[(gy << 6) | tx] : NEG4;
    }

    // column halo: 4 floats of -inf each side, one element per thread
    {
        int r = tid >> 3, s = tid & 7;
        smvm[r][(s < 4) ? s : (WW + s)] = NEG;
    }

    // vertical max-5 -> smem
    float4 a[11];
    #pragma unroll
    for (int r = 0; r < 11; r++) a[r] = f4max(v[r], v[r + 1]);
    #pragma unroll
    for (int r = 0; r < 8; r++) {
        float4 vm = f4max(f4max(a[r], a[r + 2]), v[r + 4]);
        *reinterpret_cast<float4*>(&smvm[ty * 8 + r][4 + tx * 4]) = vm;
    }
    __syncthreads();

    // horizontal max-5 + peak test + warp-aggregated emit
    #pragma unroll
    for (int r = 0; r < 8; r++) {
        const float* row = smvm[ty * 8 + r];
        float4 L = *reinterpret_cast<const float4*>(&row[tx * 4]);
        float4 C = *reinterpret_cast<const float4*>(&row[tx * 4 + 4]);
        float4 R = *reinterpret_cast<const float4*>(&row[tx * 4 + 8]);

        float m12 = fmaxf(C.y, C.z);
        float aa  = fmaxf(C.x, m12);            // max C0..C2
        float bb  = fmaxf(m12, C.w);            // max C1..C3
        float ab  = fmaxf(aa, C.w);             // max C0..C3
        float h0  = fmaxf(fmaxf(L.z, L.w), aa);
        float h1  = fmaxf(L.w, ab);
        float h2  = fmaxf(ab, R.x);
        float h3  = fmaxf(bb, fmaxf(R.x, R.y));

        float4 cen = v[r + 2];
        int m0 = (cen.x == h0), m1 = (cen.y == h1);
        int m2 = (cen.z == h2), m3 = (cen.w == h3);
        unsigned int nloc = (unsigned)(m0 + m1 + m2 + m3);

        // warp inclusive scan of nloc
        unsigned int inc = nloc;
        #pragma unroll
        for (int o = 1; o < 32; o <<= 1) {
            unsigned int t = __shfl_up_sync(0xFFFFFFFFu, inc, o);
            if (lane >= o) inc += t;
        }
        unsigned int total = __shfl_sync(0xFFFFFFFFu, inc, 31);
        if (total) {
            unsigned int base = 0;
            if (lane == 31) base = atomicAdd(&g_count[c], total);
            base = __shfl_sync(0xFFFFFFFFu, base, 31);
            unsigned int pos = base + inc - nloc;
            int rowg = y0 + ty * 8 + r;
            int col  = tx * 4;
            if (m0) { if (pos < MAXCAND) g_cand[c][pos] =
                ((unsigned long long)fkey(cen.x) << 32) | (unsigned int)(65535 - ((rowg << 8) | col)); pos++; }
            if (m1) { if (pos < MAXCAND) g_cand[c][pos] =
                ((unsigned long long)fkey(cen.y) << 32) | (unsigned int)(65535 - ((rowg << 8) | (col + 1))); pos++; }
            if (m2) { if (pos < MAXCAND) g_cand[c][pos] =
                ((unsigned long long)fkey(cen.z) << 32) | (unsigned int)(65535 - ((rowg << 8) | (col + 2))); pos++; }
            if (m3) { if (pos < MAXCAND) g_cand[c][pos] =
                ((unsigned long long)fkey(cen.w) << 32) | (unsigned int)(65535 - ((rowg << 8) | (col + 3))); pos++; }
        }
    }
}

// Find smallest bucket B with suffix_count(>=B) >= need over hist[NBKT].
// Block-collective (1024 threads). Results in out3: {B, count_above_B, suffix(B)}.
__device__ void find_boundary(const unsigned int* hist, unsigned int* psums,
                              unsigned int* wsums, unsigned int need,
                              unsigned int* out3) {
    const int tid = threadIdx.x;
    unsigned int p = 0;
    const int base = tid * 8;
    #pragma unroll
    for (int k = 0; k < 8; k++) p += hist[base + k];
    unsigned int w = p;
    #pragma unroll
    for (int o = 16; o; o >>= 1) w += __shfl_down_sync(0xFFFFFFFFu, w, o);
    psums[tid] = p;
    if ((tid & 31) == 0) wsums[tid >> 5] = w;
    __syncthreads();
    if (tid == 0) {
        unsigned int acc = 0;
        int wstar = 0;
        for (int i = 31; i >= 0; i--) {
            if (acc + wsums[i] >= need || i == 0) { wstar = i; break; }
            acc += wsums[i];
        }
        int tstar = wstar * 32;
        for (int i = wstar * 32 + 31; i >= wstar * 32; i--) {
            if (acc + psums[i] >= need || i == wstar * 32) { tstar = i; break; }
            acc += psums[i];
        }
        unsigned int B = (unsigned int)(tstar * 8);
        for (int b = tstar * 8 + 7; b >= tstar * 8; b--) {
            if (acc + hist[b] >= need || b == tstar * 8) { B = (unsigned int)b; break; }
            acc += hist[b];
        }
        out3[0] = B;
        out3[1] = acc;
        out3[2] = acc + hist[B];
    }
    __syncthreads();
}

// per-class top-100: one-pass histogram select + small bitonic sort
__global__ void class_topk_kernel() {
    __shared__ unsigned int hist[NBKT];          // 32 KB
    __shared__ unsigned int psums[1024];         // 4 KB
    __shared__ unsigned int wsums[32];
    __shared__ unsigned int bout[3];
    __shared__ unsigned long long sel[CAP];      // 8 KB
    __shared__ int s_nsel;

    const int c   = blockIdx.x;
    const int tid = threadIdx.x;
    int cnt = (int)min(g_count[c], (unsigned int)MAXCAND);
    if (tid == 0) s_nsel = 0;
    __syncthreads();

    if (cnt > CAP) {
        for (int i = tid; i < NBKT; i += 1024) hist[i] = 0;
        __syncthreads();
        for (int i = tid; i < cnt; i += 1024) {
            unsigned int fk = (unsigned int)(g_cand[c][i] >> 32);
            atomicAdd(&hist[fk >> 19], 1u);
        }
        __syncthreads();
        find_boundary(hist, psums, wsums, KTOP, bout);
        unsigned int B1 = bout[0], above = bout[1], sfx = bout[2];
        unsigned int B2 = 0;
        bool two = false;
        if (sfx > CAP) {                          // refine within boundary bucket
            two = true;
            __syncthreads();
            for (int i = tid; i < NBKT; i += 1024) hist[i] = 0;
            __syncthreads();
            for (int i = tid; i < cnt; i += 1024) {
                unsigned int fk = (unsigned int)(g_cand[c][i] >> 32);
                if ((fk >> 19) == B1) atomicAdd(&hist[(fk >> 6) & 8191u], 1u);
            }
            __syncthreads();
            find_boundary(hist, psums, wsums, KTOP - above, bout);
            B2 = bout[0];
        }
        for (int i = tid; i < cnt; i += 1024) {
            unsigned long long key = g_cand[c][i];
            unsigned int fk = (unsigned int)(key >> 32);
            unsigned int b = fk >> 19;
            bool take = (b > B1) || (b == B1 && (!two || ((fk >> 6) & 8191u) >= B2));
            if (take) {
                int pos = atomicAdd(&s_nsel, 1);
                if (pos < CAP) sel[pos] = key;
            }
        }
    } else {
        for (int i = tid; i < cnt; i += 1024) sel[i] = g_cand[c][i];
        if (tid == 0) s_nsel = cnt;
    }
    __syncthreads();

    int nsel = min(s_nsel, CAP);
    int n = 128;
    while (n < nsel) n <<= 1;
    if (tid < n && tid >= nsel) sel[tid] = 0ULL;
    __syncthreads();

    // bitonic sort n keys descending (n <= 1024, one elem per thread)
    for (int k = 2; k <= n; k <<= 1) {
        for (int j = k >> 1; j > 0; j >>= 1) {
            if (tid < n) {
                int ixj = tid ^ j;
                if (ixj > tid) {
                    unsigned long long a = sel[tid], b = sel[ixj];
                    bool up = ((tid & k) == 0);
                    if (up ? (a < b) : (a > b)) { sel[tid] = b; sel[ixj] = a; }
                }
            }
            __syncthreads();
        }
    }

    if (tid < KTOP) {
        unsigned long long key = sel[tid];
        g_topk_key[c * KTOP + tid] = (unsigned int)(key >> 32);
        g_topk_idx[c * KTOP + tid] = 65535 - (int)(key & 0xFFFFull);
    }
    if (tid == 0) g_count[c] = 0;   // reset for next launch (determinism)
}

// global top-100 over 80*100 keys via histogram select, then decode + write
__global__ void global_topk_kernel(const float* __restrict__ txty,
                                   const float* __restrict__ twth,
                                   float* __restrict__ out) {
    __shared__ unsigned int hist[NBKT];
    __shared__ unsigned int psums[1024];
    __shared__ unsigned int wsums[32];
    __shared__ unsigned int bout[3];
    __shared__ unsigned long long sel[CAP];
    __shared__ int s_nsel;

    const int tid = threadIdx.x;
    const int N = NC * KTOP;   // 8000
    if (tid == 0) s_nsel = 0;

    for (int i = tid; i < NBKT; i += 1024) hist[i] = 0;
    __syncthreads();
    for (int i = tid; i < N; i += 1024)
        atomicAdd(&hist[g_topk_key[i] >> 19], 1u);
    __syncthreads();
    find_boundary(hist, psums, wsums, KTOP, bout);
    unsigned int B1 = bout[0], above = bout[1], sfx = bout[2];
    unsigned int B2 = 0;
    bool two = false;
    if (sfx > CAP) {
        two = true;
        __syncthreads();
        for (int i = tid; i < NBKT; i += 1024) hist[i] = 0;
        __syncthreads();
        for (int i = tid; i < N; i += 1024) {
            unsigned int fk = g_topk_key[i];
            if ((fk >> 19) == B1) atomicAdd(&hist[(fk >> 6) & 8191u], 1u);
        }
        __syncthreads();
        find_boundary(hist, psums, wsums, KTOP - above, bout);
        B2 = bout[0];
    }
    for (int i = tid; i < N; i += 1024) {
        unsigned int fk = g_topk_key[i];
        unsigned int b = fk >> 19;
        bool take = (b > B1) || (b == B1 && (!two || ((fk >> 6) & 8191u) >= B2));
        if (take) {
            int pos = atomicAdd(&s_nsel, 1);
            if (pos < CAP)
                sel[pos] = ((unsigned long long)fk << 13) | (unsigned int)(8191 - i);
        }
    }
    __syncthreads();

    int nsel = min(s_nsel, CAP);
    int n = 128;
    while (n < nsel) n <<= 1;
    if (tid < n && tid >= nsel) sel[tid] = 0ULL;
    __syncthreads();

    for (int k = 2; k <= n; k <<= 1) {
        for (int j = k >> 1; j > 0; j >>= 1) {
            if (tid < n) {
                int ixj = tid ^ j;
                if (ixj > tid) {
                    unsigned long long a = sel[tid], b = sel[ixj];
                    bool up = ((tid & k) == 0);
                    if (up ? (a < b) : (a > b)) { sel[tid] = b; sel[ixj] = a; }
                }
            }
            __syncthreads();
        }
    }

    if (tid < KTOP) {
        unsigned long long key = sel[tid];
        unsigned int fk = (unsigned int)(key >> 13);
        int flat = 8191 - (int)(key & 8191ull);
        int cls = flat / KTOP;
        int spatial = g_topk_idx[flat];
        float logit = fkeyinv(fk);
        float score = 1.0f / (1.0f + expf(-logit));

        int y = spatial >> 8, x = spatial & 255;
        float tx = txty[spatial];
        float ty = txty[HWSZ + spatial];
        float tw = twth[spatial];
        float th = twth[HWSZ + spatial];

        float cx = ((float)x + 1.0f / (1.0f + expf(-tx))) * 4.0f;
        float cy = ((float)y + 1.0f / (1.0f + expf(-ty))) * 4.0f;
        float w2 = expf(tw) * 2.0f;
        float h2 = expf(th) * 2.0f;
        const float inv = 1.0f / 1024.0f;

        out[tid * 4 + 0] = fminf(fmaxf((cx - w2) * inv, 0.0f), 1.0f);
        out[tid * 4 + 1] = fminf(fmaxf((cy - h2) * inv, 0.0f), 1.0f);
        out[tid * 4 + 2] = fminf(fmaxf((cx + w2) * inv, 0.0f), 1.0f);
        out[tid * 4 + 3] = fminf(fmaxf((cy + h2) * inv, 0.0f), 1.0f);
        out[4 * KTOP + tid] = score;
        out[5 * KTOP + tid] = (float)cls;
    }
}

extern "C" void kernel_launch(void* const* d_in, const int* in_sizes, int n_in,
                              void* d_out, int out_size) {
    const float* cls  = (const float*)d_in[0];
    const float* txty = (const float*)d_in[1];
    const float* twth = (const float*)d_in[2];
    float* out = (float*)d_out;

    dim3 grid(HH / BAND, NC);
    suppress_kernel<<<grid, 256>>>(cls);
    class_topk_kernel<<<NC, 1024>>>();
    global_topk_kernel<<<1, 1024>>>(txty, twth, out);
}

// round 10
// speedup vs baseline: 7.2462x; 1.4913x over previous
#include <cuda_runtime.h>
#include <cstdint>

#define HH 256
#define WW 256
#define NC 80
#define HWSZ 65536
#define KTOP 100
#define MAXCAND 8192
#define NBKT 8192
#define CAP  1024
#define BAND 32

// scratch (no cudaMalloc allowed)
__device__ unsigned int        g_count[NC];          // zero-init at load; reset by class_topk
__device__ unsigned long long  g_cand[NC][MAXCAND];
__device__ unsigned int        g_topk_key[NC * KTOP];   // fkey(logit), sorted desc per class
__device__ int                 g_topk_idx[NC * KTOP];   // spatial index in [0,65536)

// monotone float->uint key (handles negatives)
__device__ __forceinline__ unsigned int fkey(float f) {
    unsigned int b = __float_as_uint(f);
    return b ^ ((b & 0x80000000u) ? 0xFFFFFFFFu : 0x80000000u);
}
__device__ __forceinline__ float fkeyinv(unsigned int k) {
    unsigned int b = k ^ ((k & 0x80000000u) ? 0x80000000u : 0xFFFFFFFFu);
    return __uint_as_float(b);
}
__device__ __forceinline__ float4 f4max(float4 a, float4 b) {
    return make_float4(fmaxf(a.x, b.x), fmaxf(a.y, b.y),
                       fmaxf(a.z, b.z), fmaxf(a.w, b.w));
}

// 5x5 strict-window max on logits of batch 0.
// Block = 256 threads: tx = tid&63 (float4 column group), ty = tid>>6 (8-row group).
// Phase A: 12 float4 LDG -> vertical max-5 -> smem (v[] dies at the sync).
// Phase B: horizontal max-5 from smem, centers reloaded via L1-hit LDG,
//          peak hits packed into a 32-bit register bitmask.
// Phase C: ONE warp scan + ONE atomic, then bitmask walk emits candidates.
__global__ __launch_bounds__(256, 4) void suppress_kernel(const float* __restrict__ cls) {
    __shared__ float smvm[BAND][WW + 8];            // vm + 4-col -inf halo each side
    const int c   = blockIdx.y;
    const int y0  = blockIdx.x * BAND;
    const int tid = threadIdx.x;
    const int tx  = tid & 63;
    const int ty  = tid >> 6;
    const int lane = tid & 31;
    const float NEG = __int_as_float(0xff800000);
    const float4 NEG4 = make_float4(NEG, NEG, NEG, NEG);
    const float* __restrict__ p = cls + ((size_t)c << 16);   // batch 0, class c
    const float4* __restrict__ p4 = reinterpret_cast<const float4*>(p);

    // ---- Phase A: load 12 rows (batched LDG.128), vertical max-5 -> smem ----
    {
        float4 v[12];
        const int ybase = y0 + ty * 8 - 2;
        #pragma unroll
        for (int r = 0; r < 12; r++) {
            int gy = ybase + r;
            v[r] = (gy >= 0 && gy < HH) ? p4[(gy << 6) | tx] : NEG4;
        }
        // column halo: 4 floats of -inf each side
        {
            int r = tid >> 3, s = tid & 7;
            smvm[r][(s < 4) ? s : (WW + s)] = NEG;
        }
        #pragma unroll
        for (int r = 0; r < 8; r++) {
            float4 vm = f4max(f4max(f4max(v[r], v[r + 1]),
                                    f4max(v[r + 2], v[r + 3])), v[r + 4]);
            *reinterpret_cast<float4*>(&smvm[ty * 8 + r][4 + tx * 4]) = vm;
        }
    }
    __syncthreads();

    // ---- Phase B: horizontal max-5, peak test -> register bitmask ----
    unsigned int bm = 0;
    #pragma unroll 2
    for (int r = 0; r < 8; r++) {
        const float* row = smvm[ty * 8 + r];
        float4 L = *reinterpret_cast<const float4*>(&row[tx * 4]);
        float4 C = *reinterpret_cast<const float4*>(&row[tx * 4 + 4]);
        float4 R = *reinterpret_cast<const float4*>(&row[tx * 4 + 8]);
        int rowg = y0 + ty * 8 + r;
        float4 cen = p4[(rowg << 6) | tx];          // L1 hit (just loaded in phase A)

        float m12 = fmaxf(C.y, C.z);
        float aa  = fmaxf(C.x, m12);                // max C0..C2
        float bb  = fmaxf(m12, C.w);                // max C1..C3
        float ab  = fmaxf(aa, C.w);                 // max C0..C3
        float h0  = fmaxf(fmaxf(L.z, L.w), aa);
        float h1  = fmaxf(L.w, ab);
        float h2  = fmaxf(ab, R.x);
        float h3  = fmaxf(bb, fmaxf(R.x, R.y));

        bm |= (unsigned int)(cen.x == h0) << (r * 4 + 0);
        bm |= (unsigned int)(cen.y == h1) << (r * 4 + 1);
        bm |= (unsigned int)(cen.z == h2) << (r * 4 + 2);
        bm |= (unsigned int)(cen.w == h3) << (r * 4 + 3);
    }

    // ---- Phase C: one scan, one atomic, bitmask walk ----
    unsigned int nloc = (unsigned int)__popc(bm);
    unsigned int inc = nloc;
    #pragma unroll
    for (int o = 1; o < 32; o <<= 1) {
        unsigned int t = __shfl_up_sync(0xFFFFFFFFu, inc, o);
        if (lane >= o) inc += t;
    }
    unsigned int total = __shfl_sync(0xFFFFFFFFu, inc, 31);
    if (total) {
        unsigned int base = 0;
        if (lane == 31) base = atomicAdd(&g_count[c], total);
        base = __shfl_sync(0xFFFFFFFFu, base, 31);
        unsigned int pos = base + inc - nloc;
        while (bm) {
            int b = __ffs(bm) - 1;
            bm &= bm - 1;
            int r = b >> 2, s = b & 3;
            int idx = ((y0 + ty * 8 + r) << 8) | (tx * 4 + s);
            float val = p[idx];                     // L1 hit
            if (pos < MAXCAND)
                g_cand[c][pos] = ((unsigned long long)fkey(val) << 32)
                               | (unsigned int)(65535 - idx);  // lower idx => bigger tail
            pos++;
        }
    }
}

// Find smallest bucket B with suffix_count(>=B) >= need over hist[NBKT].
// Block-collective; selection itself is warp-parallel (suffix-scan + ballot + clz).
// Results in out3: {B, count_above_B, suffix(B)}.
__device__ void find_boundary(const unsigned int* hist, unsigned int* psums,
                              unsigned int* wsums, unsigned int need,
                              unsigned int* out3) {
    const int tid = threadIdx.x;
    unsigned int pv0 = 0;
    const int base = tid * 8;
    #pragma unroll
    for (int k = 0; k < 8; k++) pv0 += hist[base + k];
    unsigned int w = pv0;
    #pragma unroll
    for (int o = 16; o; o >>= 1) w += __shfl_down_sync(0xFFFFFFFFu, w, o);
    psums[tid] = pv0;
    if ((tid & 31) == 0) wsums[tid >> 5] = w;
    __syncthreads();
    if (tid < 32) {
        // level 1: 32 warp-group sums
        unsigned int wv = wsums[tid];
        unsigned int suf = wv;
        #pragma unroll
        for (int o = 1; o < 32; o <<= 1) {
            unsigned int t = __shfl_down_sync(0xFFFFFFFFu, suf, o);
            if (tid + o < 32) suf += t;
        }
        unsigned int m = __ballot_sync(0xFFFFFFFFu, suf >= need);
        int wstar = m ? (31 - __clz(m)) : 0;
        unsigned int acc = __shfl_sync(0xFFFFFFFFu, suf - wv, wstar);  // suffix(wstar+1)
        // level 2: 32 per-thread sums within group wstar
        unsigned int pv = psums[wstar * 32 + tid];
        unsigned int sufp = pv;
        #pragma unroll
        for (int o = 1; o < 32; o <<= 1) {
            unsigned int t = __shfl_down_sync(0xFFFFFFFFu, sufp, o);
            if (tid + o < 32) sufp += t;
        }
        m = __ballot_sync(0xFFFFFFFFu, acc + sufp >= need);
        int tstar = m ? (31 - __clz(m)) : 0;
        acc = __shfl_sync(0xFFFFFFFFu, acc + sufp - pv, tstar);
        int tglob = wstar * 32 + tstar;
        // level 3: 8 hist buckets of thread tglob
        unsigned int hv = (tid < 8) ? hist[tglob * 8 + tid] : 0;
        unsigned int sufh = hv;
        #pragma unroll
        for (int o = 1; o < 8; o <<= 1) {
            unsigned int t = __shfl_down_sync(0xFFFFFFFFu, sufh, o);
            if (tid + o < 32) sufh += t;
        }
        m = __ballot_sync(0xFFFFFFFFu, (tid < 8) && (acc + sufh >= need)) & 0xFFu;
        int bstar = m ? (31 - __clz(m)) : 0;
        acc = __shfl_sync(0xFFFFFFFFu, acc + sufh - hv, bstar);
        if (tid == 0) {
            unsigned int B = (unsigned int)(tglob * 8 + bstar);
            out3[0] = B;
            out3[1] = acc;
            out3[2] = acc + hist[B];
        }
    }
    __syncthreads();
}

// per-class top-100: one-pass histogram select + small bitonic sort
__global__ void class_topk_kernel() {
    __shared__ unsigned int hist[NBKT];          // 32 KB
    __shared__ unsigned int psums[1024];         // 4 KB
    __shared__ unsigned int wsums[32];
    __shared__ unsigned int bout[3];
    __shared__ unsigned long long sel[CAP];      // 8 KB
    __shared__ int s_nsel;

    const int c   = blockIdx.x;
    const int tid = threadIdx.x;
    int cnt = (int)min(g_count[c], (unsigned int)MAXCAND);
    if (tid == 0) s_nsel = 0;
    __syncthreads();

    if (cnt > CAP) {
        for (int i = tid; i < NBKT; i += 1024) hist[i] = 0;
        __syncthreads();
        for (int i = tid; i < cnt; i += 1024) {
            unsigned int fk = (unsigned int)(g_cand[c][i] >> 32);
            atomicAdd(&hist[fk >> 19], 1u);
        }
        __syncthreads();
        find_boundary(hist, psums, wsums, KTOP, bout);
        unsigned int B1 = bout[0], above = bout[1], sfx = bout[2];
        unsigned int B2 = 0;
        bool two = false;
        if (sfx > CAP) {                          // refine within boundary bucket
            two = true;
            __syncthreads();
            for (int i = tid; i < NBKT; i += 1024) hist[i] = 0;
            __syncthreads();
            for (int i = tid; i < cnt; i += 1024) {
                unsigned int fk = (unsigned int)(g_cand[c][i] >> 32);
                if ((fk >> 19) == B1) atomicAdd(&hist[(fk >> 6) & 8191u], 1u);
            }
            __syncthreads();
            find_boundary(hist, psums, wsums, KTOP - above, bout);
            B2 = bout[0];
        }
        for (int i = tid; i < cnt; i += 1024) {
            unsigned long long key = g_cand[c][i];
            unsigned int fk = (unsigned int)(key >> 32);
            unsigned int b = fk >> 19;
            bool take = (b > B1) || (b == B1 && (!two || ((fk >> 6) & 8191u) >= B2));
            if (take) {
                int pos = atomicAdd(&s_nsel, 1);
                if (pos < CAP) sel[pos] = key;
            }
        }
    } else {
        for (int i = tid; i < cnt; i += 1024) sel[i] = g_cand[c][i];
        if (tid == 0) s_nsel = cnt;
    }
    __syncthreads();

    int nsel = min(s_nsel, CAP);
    int n = 128;
    while (n < nsel) n <<= 1;
    if (tid < n && tid >= nsel) sel[tid] = 0ULL;
    __syncthreads();

    // bitonic sort n keys descending (n <= 1024, one elem per thread)
    for (int k = 2; k <= n; k <<= 1) {
        for (int j = k >> 1; j > 0; j >>= 1) {
            if (tid < n) {
                int ixj = tid ^ j;
                if (ixj > tid) {
                    unsigned long long a = sel[tid], b = sel[ixj];
                    bool up = ((tid & k) == 0);
                    if (up ? (a < b) : (a > b)) { sel[tid] = b; sel[ixj] = a; }
                }
            }
            __syncthreads();
        }
    }

    if (tid < KTOP) {
        unsigned long long key = sel[tid];
        g_topk_key[c * KTOP + tid] = (unsigned int)(key >> 32);
        g_topk_idx[c * KTOP + tid] = 65535 - (int)(key & 0xFFFFull);
    }
    if (tid == 0) g_count[c] = 0;   // reset for next launch (determinism)
}

// global top-100 over 80*100 keys via histogram select, then decode + write
__global__ void global_topk_kernel(const float* __restrict__ txty,
                                   const float* __restrict__ twth,
                                   float* __restrict__ out) {
    __shared__ unsigned int hist[NBKT];
    __shared__ unsigned int psums[1024];
    __shared__ unsigned int wsums[32];
    __shared__ unsigned int bout[3];
    __shared__ unsigned long long sel[CAP];
    __shared__ int s_nsel;

    const int tid = threadIdx.x;
    const int N = NC * KTOP;   // 8000
    if (tid == 0) s_nsel = 0;

    for (int i = tid; i < NBKT; i += 1024) hist[i] = 0;
    __syncthreads();
    for (int i = tid; i < N; i += 1024)
        atomicAdd(&hist[g_topk_key[i] >> 19], 1u);
    __syncthreads();
    find_boundary(hist, psums, wsums, KTOP, bout);
    unsigned int B1 = bout[0], above = bout[1], sfx = bout[2];
    unsigned int B2 = 0;
    bool two = false;
    if (sfx > CAP) {
        two = true;
        __syncthreads();
        for (int i = tid; i < NBKT; i += 1024) hist[i] = 0;
        __syncthreads();
        for (int i = tid; i < N; i += 1024) {
            unsigned int fk = g_topk_key[i];
            if ((fk >> 19) == B1) atomicAdd(&hist[(fk >> 6) & 8191u], 1u);
        }
        __syncthreads();
        find_boundary(hist, psums, wsums, KTOP - above, bout);
        B2 = bout[0];
    }
    for (int i = tid; i < N; i += 1024) {
        unsigned int fk = g_topk_key[i];
        unsigned int b = fk >> 19;
        bool take = (b > B1) || (b == B1 && (!two || ((fk >> 6) & 8191u) >= B2));
        if (take) {
            int pos = atomicAdd(&s_nsel, 1);
            if (pos < CAP)
                sel[pos] = ((unsigned long long)fk << 13) | (unsigned int)(8191 - i);
        }
    }
    __syncthreads();

    int nsel = min(s_nsel, CAP);
    int n = 128;
    while (n < nsel) n <<= 1;
    if (tid < n && tid >= nsel) sel[tid] = 0ULL;
    __syncthreads();

    for (int k = 2; k <= n; k <<= 1) {
        for (int j = k >> 1; j > 0; j >>= 1) {
            if (tid < n) {
                int ixj = tid ^ j;
                if (ixj > tid) {
                    unsigned long long a = sel[tid], b = sel[ixj];
                    bool up = ((tid & k) == 0);
                    if (up ? (a < b) : (a > b)) { sel[tid] = b; sel[ixj] = a; }
                }
            }
            __syncthreads();
        }
    }

    if (tid < KTOP) {
        unsigned long long key = sel[tid];
        unsigned int fk = (unsigned int)(key >> 13);
        int flat = 8191 - (int)(key & 8191ull);
        int cls = flat / KTOP;
        int spatial = g_topk_idx[flat];
        float logit = fkeyinv(fk);
        float score = 1.0f / (1.0f + expf(-logit));

        int y = spatial >> 8, x = spatial & 255;
        float tx = txty[spatial];
        float ty = txty[HWSZ + spatial];
        float tw = twth[spatial];
        float th = twth[HWSZ + spatial];

        float cx = ((float)x + 1.0f / (1.0f + expf(-tx))) * 4.0f;
        float cy = ((float)y + 1.0f / (1.0f + expf(-ty))) * 4.0f;
        float w2 = expf(tw) * 2.0f;
        float h2 = expf(th) * 2.0f;
        const float inv = 1.0f / 1024.0f;

        out[tid * 4 + 0] = fminf(fmaxf((cx - w2) * inv, 0.0f), 1.0f);
        out[tid * 4 + 1] = fminf(fmaxf((cy - h2) * inv, 0.0f), 1.0f);
        out[tid * 4 + 2] = fminf(fmaxf((cx + w2) * inv, 0.0f), 1.0f);
        out[tid * 4 + 3] = fminf(fmaxf((cy + h2) * inv, 0.0f), 1.0f);
        out[4 * KTOP + tid] = score;
        out[5 * KTOP + tid] = (float)cls;
    }
}

extern "C" void kernel_launch(void* const* d_in, const int* in_sizes, int n_in,
                              void* d_out, int out_size) {
    const float* cls  = (const float*)d_in[0];
    const float* txty = (const float*)d_in[1];
    const float* twth = (const float*)d_in[2];
    float* out = (float*)d_out;

    dim3 grid(HH / BAND, NC);
    suppress_kernel<<<grid, 256>>>(cls);
    class_topk_kernel<<<NC, 1024>>>();
    global_topk_kernel<<<1, 1024>>>(txty, twth, out);
}